// round 5
// baseline (speedup 1.0000x reference)
#include <cuda_runtime.h>
#include <cuda_bf16.h>
#include <math.h>
#include <stdint.h>

// Problem constants
#define N_TOK   524288
#define P_TOK   64
#define C_DIM   128
#define M_PART  4096
#define MW_CNT  262144
#define A_CNT   131072
#define BL_CNT  65536
#define EPS_LN  1e-6f

// ---------------------------------------------------------------------------
// Scratch (device globals — allocation-free rule)
// ---------------------------------------------------------------------------
__device__ float g_xa[(size_t)A_CNT * C_DIM];            // double-LN asy rows (rank order)
__device__ float g_att[(size_t)A_CNT * C_DIM];           // proj output for asy rows
__device__ float g_y[(size_t)A_CNT * C_DIM];             // MLP residual input
__device__ float g_yn[(size_t)A_CNT * C_DIM];            // LN2(y)
__device__ __nv_bfloat16 g_qkv_bf[(size_t)MW_CNT * 384]; // QKV output (bf16)
__device__ __nv_bfloat16 g_o_bf[(size_t)MW_CNT * C_DIM]; // attention output (bf16)
__device__ __nv_bfloat16 g_h_bf[(size_t)A_CNT * 512];    // MLP hidden (bf16)
__device__ unsigned char g_flag[MW_CNT];                 // 0 none, 1 asy, 2 blocked
__device__ int g_rank[MW_CNT];
__device__ int g_asyrow[A_CNT];                          // window row of asy[i]
__device__ unsigned char g_mflag[MW_CNT];                // partition-order meta
__device__ int g_mrow[MW_CNT];
__device__ int g_mrank[MW_CNT];

// ---------------------------------------------------------------------------
// helpers
// ---------------------------------------------------------------------------
__device__ __forceinline__ float warp_sum(float v) {
#pragma unroll
    for (int o = 16; o; o >>= 1) v += __shfl_xor_sync(0xffffffffu, v, o);
    return v;
}
__device__ __forceinline__ void mma_tf32(float c[4], const uint32_t a[4], const uint32_t b[2]) {
    asm volatile(
        "mma.sync.aligned.m16n8k8.row.col.f32.tf32.tf32.f32 "
        "{%0,%1,%2,%3}, {%4,%5,%6,%7}, {%8,%9}, {%0,%1,%2,%3};"
        : "+f"(c[0]), "+f"(c[1]), "+f"(c[2]), "+f"(c[3])
        : "r"(a[0]), "r"(a[1]), "r"(a[2]), "r"(a[3]), "r"(b[0]), "r"(b[1]));
}
__device__ __forceinline__ uint32_t smem_u32(const void* p) {
    uint32_t a;
    asm("{ .reg .u64 t; cvta.to.shared.u64 t, %1; cvt.u32.u64 %0, t; }" : "=r"(a) : "l"(p));
    return a;
}
__device__ __forceinline__ void cp_async16(uint32_t dst, const void* src) {
    asm volatile("cp.async.cg.shared.global [%0], [%1], 16;" :: "r"(dst), "l"(src) : "memory");
}

// ---------------------------------------------------------------------------
// K1: X = LN(x) for all rows -> d_out
// ---------------------------------------------------------------------------
__global__ void __launch_bounds__(256) ln_kernel(
    const float* __restrict__ x, const float* __restrict__ w,
    const float* __restrict__ b, float* __restrict__ out)
{
    int row  = (int)((blockIdx.x * 256u + threadIdx.x) >> 5);
    int lane = threadIdx.x & 31;
    if (row >= N_TOK) return;
    float4 v = reinterpret_cast<const float4*>(x + (size_t)row * C_DIM)[lane];
    float m = warp_sum(v.x + v.y + v.z + v.w) * (1.0f / C_DIM);
    float dx = v.x - m, dy = v.y - m, dz = v.z - m, dw = v.w - m;
    float var = warp_sum(dx*dx + dy*dy + dz*dz + dw*dw) * (1.0f / C_DIM);
    float inv = rsqrtf(var + EPS_LN);
    float4 wv = reinterpret_cast<const float4*>(w)[lane];
    float4 bv = reinterpret_cast<const float4*>(b)[lane];
    float4 r;
    r.x = dx * inv * wv.x + bv.x; r.y = dy * inv * wv.y + bv.y;
    r.z = dz * inv * wv.z + bv.z; r.w = dw * inv * wv.w + bv.w;
    reinterpret_cast<float4*>(out + (size_t)row * C_DIM)[lane] = r;
}

// ---------------------------------------------------------------------------
// K2/K3/K4: flag + rank + partition-order meta
// ---------------------------------------------------------------------------
__global__ void __launch_bounds__(256) zero_flags_kernel()
{
    int t = blockIdx.x * 256 + threadIdx.x;
    if (t < MW_CNT / 16)
        reinterpret_cast<uint4*>(g_flag)[t] = make_uint4(0u, 0u, 0u, 0u);
}
__global__ void __launch_bounds__(256) set_flags_kernel(
    const int* __restrict__ asy, const int* __restrict__ blk, const int* __restrict__ iw)
{
    int t = blockIdx.x * 256 + threadIdx.x;
    if (t < A_CNT) {
        int g = asy[t];
        g_flag[g] = 1;
        g_rank[g] = t;
        g_asyrow[t] = iw[g >> 6] * 64 + (g & 63);
    } else if (t < A_CNT + BL_CNT) {
        g_flag[blk[t - A_CNT]] = 2;
    }
}
__global__ void __launch_bounds__(256) meta_kernel(
    const int* __restrict__ ipart, const int* __restrict__ iw)
{
    int i = blockIdx.x * 256 + threadIdx.x;
    if (i >= MW_CNT) return;
    int g = ipart[i];
    int f = g_flag[g];
    g_mflag[i] = (unsigned char)f;
    g_mrow[i]  = iw[g >> 6] * 64 + (g & 63);
    g_mrank[i] = (f == 1) ? g_rank[g] : 0;
}

// ---------------------------------------------------------------------------
// K5: xa = LN(X[window row of asy[i]]) -> g_xa
// ---------------------------------------------------------------------------
__global__ void __launch_bounds__(256) xa_kernel(
    const float* __restrict__ X, const int* __restrict__ asy,
    const int* __restrict__ iw,
    const float* __restrict__ w, const float* __restrict__ b)
{
    int i    = (int)((blockIdx.x * 256u + threadIdx.x) >> 5);
    int lane = threadIdx.x & 31;
    if (i >= A_CNT) return;
    int g = asy[i];
    int src = iw[g >> 6] * 64 + (g & 63);
    float4 v = reinterpret_cast<const float4*>(X + (size_t)src * C_DIM)[lane];
    float m = warp_sum(v.x + v.y + v.z + v.w) * (1.0f / C_DIM);
    float dx = v.x - m, dy = v.y - m, dz = v.z - m, dw = v.w - m;
    float var = warp_sum(dx*dx + dy*dy + dz*dz + dw*dw) * (1.0f / C_DIM);
    float inv = rsqrtf(var + EPS_LN);
    float4 wv = reinterpret_cast<const float4*>(w)[lane];
    float4 bv = reinterpret_cast<const float4*>(b)[lane];
    float4 r;
    r.x = dx * inv * wv.x + bv.x; r.y = dy * inv * wv.y + bv.y;
    r.z = dz * inv * wv.z + bv.z; r.w = dw * inv * wv.w + bv.w;
    reinterpret_cast<float4*>(g_xa + (size_t)i * C_DIM)[lane] = r;
}

// ---------------------------------------------------------------------------
// GEMM v3: tf32 warp-MMA, 128x128 block tile, cp.async double-buffered.
//   8 warps 4x2, warp tile 32x64 (2x8 m16n8k8 fragments).
//   AMODE 0: A fp32 contiguous     AMODE 1: A gathered per-row (QKV)
//   AMODE 2: A bf16 contiguous
//   EPI 0: +bias -> out            EPI 1: +bias, scatter via g_m* meta
//   EPI 2: +bias, gelu -> out      EPI 3: +bias, g_y + evec*acc -> out[g_asyrow]
//   OBF  : write output as bf16 (EPI 0/2)
// ---------------------------------------------------------------------------
#define AS_STRIDE 36
#define BS_STRIDE 136
#define GEMM_ASZ (128 * AS_STRIDE)
#define GEMM_BSZ (32 * BS_STRIDE)
#define GEMM_SMEM_BYTES ((2 * GEMM_ASZ + 2 * GEMM_BSZ) * 4)

template<int NTOT, int KTOT, int EPI, int AMODE, int OBF>
__global__ void __launch_bounds__(256) gemm3_kernel(
    const void* __restrict__ Avoid, const float* __restrict__ W,
    const float* __restrict__ bias, void* __restrict__ outv,
    const float* __restrict__ evec, const float* __restrict__ Xbase)
{
    extern __shared__ float smf[];
    float* As = smf;                       // 2 stages of 128x32 (stride 36)
    float* Bs = smf + 2 * GEMM_ASZ;        // 2 stages of 32x128 (stride 136)

    int tid  = threadIdx.x;
    int lane = tid & 31;
    int wid  = tid >> 5;
    int wr   = wid >> 1;
    int wc   = wid & 1;
    int g    = lane >> 2;
    int tg   = lane & 3;
    size_t m0 = (size_t)blockIdx.x * 128;
    int n0 = blockIdx.y * 128;
    constexpr int NC = KTOT / 32;

    uint32_t as_u = smem_u32(As);
    uint32_t bs_u = smem_u32(Bs);

    // per-thread A source row pointers (AMODE 1: gathered)
    const float* rowp[4];
    if constexpr (AMODE == 1) {
#pragma unroll
        for (int t = 0; t < 4; t++) {
            size_t grow = m0 + ((tid + t * 256) >> 3);
            int f = g_mflag[grow];
            rowp[t] = (f == 1) ? (g_xa + (size_t)g_mrank[grow] * C_DIM)
                               : (Xbase + (size_t)g_mrow[grow] * C_DIM);
        }
    }

    auto load_chunk = [&](int kc, int s) {
        if constexpr (AMODE == 0) {
            const float* A = (const float*)Avoid;
#pragma unroll
            for (int t = 0; t < 4; t++) {
                int idx = tid + t * 256;
                int r = idx >> 3, cc = (idx & 7) * 4;
                cp_async16(as_u + (uint32_t)(s * GEMM_ASZ + r * AS_STRIDE + cc) * 4,
                           A + (m0 + r) * KTOT + kc * 32 + cc);
            }
        } else if constexpr (AMODE == 1) {
#pragma unroll
            for (int t = 0; t < 4; t++) {
                int idx = tid + t * 256;
                int r = idx >> 3, cc = (idx & 7) * 4;
                cp_async16(as_u + (uint32_t)(s * GEMM_ASZ + r * AS_STRIDE + cc) * 4,
                           rowp[t] + kc * 32 + cc);
            }
        } else {
            const __nv_bfloat16* Ab = (const __nv_bfloat16*)Avoid;
#pragma unroll
            for (int t = 0; t < 2; t++) {
                int idx = tid + t * 256;
                int r = idx >> 2, cc = (idx & 3) * 8;
                uint4 u = *reinterpret_cast<const uint4*>(
                    Ab + (m0 + r) * KTOT + kc * 32 + cc);
                float2 f0 = __bfloat1622float2(*reinterpret_cast<__nv_bfloat162*>(&u.x));
                float2 f1 = __bfloat1622float2(*reinterpret_cast<__nv_bfloat162*>(&u.y));
                float2 f2 = __bfloat1622float2(*reinterpret_cast<__nv_bfloat162*>(&u.z));
                float2 f3 = __bfloat1622float2(*reinterpret_cast<__nv_bfloat162*>(&u.w));
                float* d = &As[s * GEMM_ASZ + r * AS_STRIDE + cc];
                *reinterpret_cast<float4*>(d)     = make_float4(f0.x, f0.y, f1.x, f1.y);
                *reinterpret_cast<float4*>(d + 4) = make_float4(f2.x, f2.y, f3.x, f3.y);
            }
        }
#pragma unroll
        for (int t = 0; t < 4; t++) {
            int idx = tid + t * 256;
            int r = idx >> 5, cc = (idx & 31) * 4;
            cp_async16(bs_u + (uint32_t)(s * GEMM_BSZ + r * BS_STRIDE + cc) * 4,
                       W + (size_t)(kc * 32 + r) * NTOT + n0 + cc);
        }
        asm volatile("cp.async.commit_group;" ::: "memory");
    };

    float c[2][8][4];
#pragma unroll
    for (int i = 0; i < 2; i++)
#pragma unroll
        for (int j = 0; j < 8; j++)
#pragma unroll
            for (int q = 0; q < 4; q++) c[i][j][q] = 0.0f;

    load_chunk(0, 0);
    for (int kc = 0; kc < NC; kc++) {
        int s = kc & 1;
        if (kc + 1 < NC) {
            load_chunk(kc + 1, (kc + 1) & 1);
            asm volatile("cp.async.wait_group 1;" ::: "memory");
        } else {
            asm volatile("cp.async.wait_group 0;" ::: "memory");
        }
        __syncthreads();
        const float* Ap = As + s * GEMM_ASZ;
        const float* Bp = Bs + s * GEMM_BSZ;
#pragma unroll
        for (int kb = 0; kb < 4; kb++) {
            uint32_t a[2][4], b[8][2];
#pragma unroll
            for (int i = 0; i < 2; i++) {
                int row = wr * 32 + i * 16 + g;
                a[i][0] = __float_as_uint(Ap[row * AS_STRIDE + kb * 8 + tg]);
                a[i][1] = __float_as_uint(Ap[(row + 8) * AS_STRIDE + kb * 8 + tg]);
                a[i][2] = __float_as_uint(Ap[row * AS_STRIDE + kb * 8 + tg + 4]);
                a[i][3] = __float_as_uint(Ap[(row + 8) * AS_STRIDE + kb * 8 + tg + 4]);
            }
#pragma unroll
            for (int j = 0; j < 8; j++) {
                int n = wc * 64 + j * 8 + g;
                b[j][0] = __float_as_uint(Bp[(kb * 8 + tg) * BS_STRIDE + n]);
                b[j][1] = __float_as_uint(Bp[(kb * 8 + tg + 4) * BS_STRIDE + n]);
            }
#pragma unroll
            for (int i = 0; i < 2; i++)
#pragma unroll
                for (int j = 0; j < 8; j++)
                    mma_tf32(c[i][j], a[i], b[j]);
        }
        __syncthreads();
    }

    // ---- epilogue ----
#pragma unroll
    for (int i = 0; i < 2; i++) {
#pragma unroll
        for (int half = 0; half < 2; half++) {
            size_t grow = m0 + wr * 32 + i * 16 + g + half * 8;
            float* dstf = nullptr;
            int f = 0;
            if constexpr (EPI == 1) {
                f = g_mflag[grow];
                dstf = (f == 1) ? (g_att + (size_t)g_mrank[grow] * C_DIM)
                                : ((float*)outv + (size_t)g_mrow[grow] * C_DIM);
            } else if constexpr (EPI == 3) {
                dstf = (float*)outv + (size_t)g_asyrow[grow] * C_DIM;
            }
#pragma unroll
            for (int j = 0; j < 8; j++) {
                int colg = n0 + wc * 64 + j * 8 + tg * 2;
                float v0 = c[i][j][half * 2]     + __ldg(&bias[colg]);
                float v1 = c[i][j][half * 2 + 1] + __ldg(&bias[colg + 1]);
                if constexpr (EPI == 2) {
                    v0 = 0.5f * v0 * (1.0f + erff(v0 * 0.7071067811865476f));
                    v1 = 0.5f * v1 * (1.0f + erff(v1 * 0.7071067811865476f));
                }
                if constexpr (EPI == 3) {
                    v0 = g_y[grow * C_DIM + colg]     + __ldg(&evec[colg]) * v0;
                    v1 = g_y[grow * C_DIM + colg + 1] + __ldg(&evec[colg + 1]) * v1;
                }
                if constexpr (EPI == 1) {
                    if (f != 2)
                        *reinterpret_cast<float2*>(dstf + colg) = make_float2(v0, v1);
                } else if constexpr (EPI == 3) {
                    *reinterpret_cast<float2*>(dstf + colg) = make_float2(v0, v1);
                } else if constexpr (OBF) {
                    *reinterpret_cast<__nv_bfloat162*>(
                        (__nv_bfloat16*)outv + grow * NTOT + colg) =
                        __floats2bfloat162_rn(v0, v1);
                } else {
                    *reinterpret_cast<float2*>((float*)outv + grow * NTOT + colg) =
                        make_float2(v0, v1);
                }
            }
        }
    }
}

// ---------------------------------------------------------------------------
// K7: tensor-core attention per partition. g_qkv_bf (64x384) -> g_o_bf (64x128).
// ---------------------------------------------------------------------------
#define QS3 388
#define SS3 66
#define ATTN3_SMEM_BYTES ((64 * QS3 + 4 * 64 * SS3) * 4 + 256)

__global__ void __launch_bounds__(256, 1) attn3_kernel(
    const __nv_bfloat16* __restrict__ gqkv, __nv_bfloat16* __restrict__ go)
{
    extern __shared__ float sm[];
    float* qsm = sm;                         // 64 x QS3
    float* ssm = sm + 64 * QS3;              // 4 heads x 64 x SS3
    int* kfl   = (int*)(ssm + 4 * 64 * SS3); // 64

    int m   = blockIdx.x;
    int tid = threadIdx.x;
    if (tid < 64) kfl[tid] = g_mflag[m * 64 + tid];

    const uint4* src = reinterpret_cast<const uint4*>(gqkv + (size_t)m * 64 * 384);
    for (int i = tid; i < 3072; i += 256) {
        int r = i / 48, c8 = (i - r * 48) * 8;
        uint4 u = src[i];
        float2 f0 = __bfloat1622float2(*reinterpret_cast<__nv_bfloat162*>(&u.x));
        float2 f1 = __bfloat1622float2(*reinterpret_cast<__nv_bfloat162*>(&u.y));
        float2 f2 = __bfloat1622float2(*reinterpret_cast<__nv_bfloat162*>(&u.z));
        float2 f3 = __bfloat1622float2(*reinterpret_cast<__nv_bfloat162*>(&u.w));
        float* d = &qsm[r * QS3 + c8];
        d[0] = f0.x; d[1] = f0.y; d[2] = f1.x; d[3] = f1.y;
        d[4] = f2.x; d[5] = f2.y; d[6] = f3.x; d[7] = f3.y;
    }
    __syncthreads();

    int wid = tid >> 5, lane = tid & 31;
    int g = lane >> 2, tg = lane & 3;
    int h = wid >> 1;
    int rbase = (wid & 1) * 32;
    int bq = h * 96, bk = bq + 32, bv = bq + 64;
    float* ssh = ssm + h * 64 * SS3;
    const float scale = 0.17677669529663687f;

    // ---- S = Q K^T ----
    float c[2][8][4];
#pragma unroll
    for (int i = 0; i < 2; i++)
#pragma unroll
        for (int j = 0; j < 8; j++)
#pragma unroll
            for (int q = 0; q < 4; q++) c[i][j][q] = 0.0f;

#pragma unroll
    for (int kt = 0; kt < 4; kt++) {
        uint32_t a[2][4], b[8][2];
#pragma unroll
        for (int i = 0; i < 2; i++) {
            int row = rbase + i * 16 + g;
            a[i][0] = __float_as_uint(qsm[row * QS3 + bq + kt * 8 + tg]);
            a[i][1] = __float_as_uint(qsm[(row + 8) * QS3 + bq + kt * 8 + tg]);
            a[i][2] = __float_as_uint(qsm[row * QS3 + bq + kt * 8 + tg + 4]);
            a[i][3] = __float_as_uint(qsm[(row + 8) * QS3 + bq + kt * 8 + tg + 4]);
        }
#pragma unroll
        for (int j = 0; j < 8; j++) {
            int n = j * 8 + g;
            b[j][0] = __float_as_uint(qsm[n * QS3 + bk + kt * 8 + tg]);
            b[j][1] = __float_as_uint(qsm[n * QS3 + bk + kt * 8 + tg + 4]);
        }
#pragma unroll
        for (int i = 0; i < 2; i++)
#pragma unroll
            for (int j = 0; j < 8; j++)
                mma_tf32(c[i][j], a[i], b[j]);
    }

    // ---- mask bits ----
    unsigned mask = 0;
#pragma unroll
    for (int j = 0; j < 8; j++)
#pragma unroll
        for (int q = 0; q < 2; q++)
            if (kfl[j * 8 + 2 * tg + q] == 2) mask |= 1u << (j * 2 + q);

    // ---- register softmax (quad shuffles) ----
#pragma unroll
    for (int i = 0; i < 2; i++) {
#pragma unroll
        for (int sel = 0; sel < 2; sel++) {
            float mx = -1e30f;
#pragma unroll
            for (int j = 0; j < 8; j++)
#pragma unroll
                for (int q = 0; q < 2; q++) {
                    float v = c[i][j][sel * 2 + q] * scale;
                    if (mask & (1u << (j * 2 + q))) v = -10000.0f;
                    c[i][j][sel * 2 + q] = v;
                    mx = fmaxf(mx, v);
                }
            mx = fmaxf(mx, __shfl_xor_sync(0xffffffffu, mx, 1));
            mx = fmaxf(mx, __shfl_xor_sync(0xffffffffu, mx, 2));
            float s = 0.0f;
#pragma unroll
            for (int j = 0; j < 8; j++)
#pragma unroll
                for (int q = 0; q < 2; q++) {
                    float e = __expf(c[i][j][sel * 2 + q] - mx);
                    c[i][j][sel * 2 + q] = e;
                    s += e;
                }
            s += __shfl_xor_sync(0xffffffffu, s, 1);
            s += __shfl_xor_sync(0xffffffffu, s, 2);
            float rinv = 1.0f / s;
            int row = rbase + i * 16 + g + sel * 8;
#pragma unroll
            for (int j = 0; j < 8; j++)
#pragma unroll
                for (int q = 0; q < 2; q++)
                    ssh[row * SS3 + j * 8 + 2 * tg + q] = c[i][j][sel * 2 + q] * rinv;
        }
    }
    __syncwarp();

    // ---- O = P @ V ----
    float o[2][4][4];
#pragma unroll
    for (int i = 0; i < 2; i++)
#pragma unroll
        for (int j = 0; j < 4; j++)
#pragma unroll
            for (int q = 0; q < 4; q++) o[i][j][q] = 0.0f;

#pragma unroll
    for (int kt = 0; kt < 8; kt++) {
        uint32_t a[2][4], b[4][2];
#pragma unroll
        for (int i = 0; i < 2; i++) {
            int row = rbase + i * 16 + g;
            a[i][0] = __float_as_uint(ssh[row * SS3 + kt * 8 + tg]);
            a[i][1] = __float_as_uint(ssh[(row + 8) * SS3 + kt * 8 + tg]);
            a[i][2] = __float_as_uint(ssh[row * SS3 + kt * 8 + tg + 4]);
            a[i][3] = __float_as_uint(ssh[(row + 8) * SS3 + kt * 8 + tg + 4]);
        }
#pragma unroll
        for (int j = 0; j < 4; j++) {
            int n = j * 8 + g;
            b[j][0] = __float_as_uint(qsm[(kt * 8 + tg) * QS3 + bv + n]);
            b[j][1] = __float_as_uint(qsm[(kt * 8 + tg + 4) * QS3 + bv + n]);
        }
#pragma unroll
        for (int i = 0; i < 2; i++)
#pragma unroll
            for (int j = 0; j < 4; j++)
                mma_tf32(o[i][j], a[i], b[j]);
    }

#pragma unroll
    for (int i = 0; i < 2; i++)
#pragma unroll
        for (int j = 0; j < 4; j++) {
            size_t row = (size_t)(m * 64 + rbase + i * 16 + g);
            int col = h * 32 + j * 8 + 2 * tg;
            *reinterpret_cast<__nv_bfloat162*>(&go[row * C_DIM + col]) =
                __floats2bfloat162_rn(o[i][j][0], o[i][j][1]);
            *reinterpret_cast<__nv_bfloat162*>(&go[(row + 8) * C_DIM + col]) =
                __floats2bfloat162_rn(o[i][j][2], o[i][j][3]);
        }
}

// ---------------------------------------------------------------------------
// K8: y = xa + g1*att -> g_y ; g_yn = LN2(y).
// ---------------------------------------------------------------------------
__global__ void __launch_bounds__(256) ybuild_kernel(
    const float* __restrict__ g1,
    const float* __restrict__ ln2w, const float* __restrict__ ln2b)
{
    int r    = (int)((blockIdx.x * 256u + threadIdx.x) >> 5);
    int lane = threadIdx.x & 31;
    if (r >= A_CNT) return;
    float4 a = reinterpret_cast<const float4*>(g_xa + (size_t)r * C_DIM)[lane];
    float4 t = reinterpret_cast<const float4*>(g_att + (size_t)r * C_DIM)[lane];
    float4 gv = reinterpret_cast<const float4*>(g1)[lane];
    float4 y;
    y.x = a.x + gv.x * t.x; y.y = a.y + gv.y * t.y;
    y.z = a.z + gv.z * t.z; y.w = a.w + gv.w * t.w;
    reinterpret_cast<float4*>(g_y + (size_t)r * C_DIM)[lane] = y;
    float m = warp_sum(y.x + y.y + y.z + y.w) * (1.0f / C_DIM);
    float dx = y.x - m, dy = y.y - m, dz = y.z - m, dw = y.w - m;
    float var = warp_sum(dx*dx + dy*dy + dz*dz + dw*dw) * (1.0f / C_DIM);
    float inv = rsqrtf(var + EPS_LN);
    float4 wv = reinterpret_cast<const float4*>(ln2w)[lane];
    float4 bv = reinterpret_cast<const float4*>(ln2b)[lane];
    float4 o;
    o.x = dx * inv * wv.x + bv.x; o.y = dy * inv * wv.y + bv.y;
    o.z = dz * inv * wv.z + bv.z; o.w = dw * inv * wv.w + bv.w;
    reinterpret_cast<float4*>(g_yn + (size_t)r * C_DIM)[lane] = o;
}

// ---------------------------------------------------------------------------
extern "C" void kernel_launch(void* const* d_in, const int* in_sizes, int n_in,
                              void* d_out, int out_size)
{
    int base = 7;
    if (n_in == 19) base = 5;

    const float* x      = (const float*)d_in[0];
    const int*   iw     = (const int*)d_in[1];
    const int*   ipart  = (const int*)d_in[2];
    const int*   asy    = (const int*)d_in[3];
    const int*   blk    = (const int*)d_in[4];
    const float* ln1w   = (const float*)d_in[base + 0];
    const float* ln1b   = (const float*)d_in[base + 1];
    const float* qkvw   = (const float*)d_in[base + 2];
    const float* qkvb   = (const float*)d_in[base + 3];
    const float* projw  = (const float*)d_in[base + 4];
    const float* projb  = (const float*)d_in[base + 5];
    const float* g1     = (const float*)d_in[base + 6];
    const float* ln2w   = (const float*)d_in[base + 7];
    const float* ln2b   = (const float*)d_in[base + 8];
    const float* w1     = (const float*)d_in[base + 9];
    const float* b1     = (const float*)d_in[base + 10];
    const float* w2     = (const float*)d_in[base + 11];
    const float* b2     = (const float*)d_in[base + 12];
    const float* g2     = (const float*)d_in[base + 13];
    float* out = (float*)d_out;

    __nv_bfloat16 *p_qkv_bf, *p_o_bf, *p_h_bf;
    float *p_yn;
    cudaGetSymbolAddress((void**)&p_qkv_bf, g_qkv_bf);
    cudaGetSymbolAddress((void**)&p_o_bf, g_o_bf);
    cudaGetSymbolAddress((void**)&p_h_bf, g_h_bf);
    cudaGetSymbolAddress((void**)&p_yn, g_yn);

    cudaFuncSetAttribute(gemm3_kernel<384, 128, 0, 1, 1>,
                         cudaFuncAttributeMaxDynamicSharedMemorySize, GEMM_SMEM_BYTES);
    cudaFuncSetAttribute(gemm3_kernel<128, 128, 1, 2, 0>,
                         cudaFuncAttributeMaxDynamicSharedMemorySize, GEMM_SMEM_BYTES);
    cudaFuncSetAttribute(gemm3_kernel<512, 128, 2, 0, 1>,
                         cudaFuncAttributeMaxDynamicSharedMemorySize, GEMM_SMEM_BYTES);
    cudaFuncSetAttribute(gemm3_kernel<128, 512, 3, 2, 0>,
                         cudaFuncAttributeMaxDynamicSharedMemorySize, GEMM_SMEM_BYTES);
    cudaFuncSetAttribute(attn3_kernel,
                         cudaFuncAttributeMaxDynamicSharedMemorySize, ATTN3_SMEM_BYTES);

    // 1. X = LN(x)
    ln_kernel<<<N_TOK / 8, 256>>>(x, ln1w, ln1b, out);
    // 2-4. flag/rank/meta maps
    zero_flags_kernel<<<(MW_CNT / 16 + 255) / 256, 256>>>();
    set_flags_kernel<<<(A_CNT + BL_CNT + 255) / 256, 256>>>(asy, blk, iw);
    meta_kernel<<<MW_CNT / 256, 256>>>(ipart, iw);
    // 5. xa double-LN
    xa_kernel<<<A_CNT / 8, 256>>>(out, asy, iw, ln1w, ln1b);
    // 6. QKV GEMM with fused gather -> bf16
    gemm3_kernel<384, 128, 0, 1, 1><<<dim3(MW_CNT / 128, 3), 256, GEMM_SMEM_BYTES>>>(
        nullptr, qkvw, qkvb, p_qkv_bf, nullptr, out);
    // 7. attention (tensor cores) -> bf16
    attn3_kernel<<<M_PART, 256, ATTN3_SMEM_BYTES>>>(p_qkv_bf, p_o_bf);
    // 8. proj GEMM (bf16 A) + scatter
    gemm3_kernel<128, 128, 1, 2, 0><<<dim3(MW_CNT / 128, 1), 256, GEMM_SMEM_BYTES>>>(
        p_o_bf, projw, projb, out, nullptr, nullptr);
    // 9. y build + LN2
    ybuild_kernel<<<A_CNT / 8, 256>>>(g1, ln2w, ln2b);
    // 10. MLP GEMM1 + gelu -> bf16
    gemm3_kernel<512, 128, 2, 0, 1><<<dim3(A_CNT / 128, 4), 256, GEMM_SMEM_BYTES>>>(
        p_yn, w1, b1, p_h_bf, nullptr, nullptr);
    // 11. MLP GEMM2 (bf16 A) + residual + scatter
    gemm3_kernel<128, 512, 3, 2, 0><<<dim3(A_CNT / 128, 1), 256, GEMM_SMEM_BYTES>>>(
        p_h_bf, w2, b2, out, g2, nullptr);
}

// round 6
// speedup vs baseline: 1.0070x; 1.0070x over previous
#include <cuda_runtime.h>
#include <cuda_bf16.h>
#include <math.h>
#include <stdint.h>

// Problem constants
#define N_TOK   524288
#define P_TOK   64
#define C_DIM   128
#define M_PART  4096
#define MW_CNT  262144
#define A_CNT   131072
#define BL_CNT  65536
#define EPS_LN  1e-6f

// ---------------------------------------------------------------------------
// Scratch (device globals — allocation-free rule)
// ---------------------------------------------------------------------------
__device__ float g_xa[(size_t)A_CNT * C_DIM];            // double-LN asy rows (rank order)
__device__ float g_att[(size_t)A_CNT * C_DIM];           // proj output for asy rows
__device__ float g_y[(size_t)A_CNT * C_DIM];             // MLP residual input
__device__ __nv_bfloat16 g_xp_bf[(size_t)MW_CNT * C_DIM];  // gathered attn input (bf16)
__device__ __nv_bfloat16 g_qkv_bf[(size_t)MW_CNT * 384];   // QKV output (bf16)
__device__ __nv_bfloat16 g_o_bf[(size_t)MW_CNT * C_DIM];   // attention output (bf16)
__device__ __nv_bfloat16 g_yn_bf[(size_t)A_CNT * C_DIM];   // LN2(y) (bf16)
__device__ __nv_bfloat16 g_h_bf[(size_t)A_CNT * 512];      // MLP hidden (bf16)
__device__ unsigned char g_flag[MW_CNT];                 // 0 none, 1 asy, 2 blocked
__device__ int g_rank[MW_CNT];
__device__ int g_asyrow[A_CNT];                          // window row of asy[i]
__device__ int g_invrank[N_TOK];                         // window row -> asy rank (-1)
__device__ unsigned char g_mflag[MW_CNT];                // partition-order meta
__device__ int g_mrow[MW_CNT];
__device__ int g_mrank[MW_CNT];

// ---------------------------------------------------------------------------
// helpers
// ---------------------------------------------------------------------------
__device__ __forceinline__ void mma_tf32(float c[4], const uint32_t a[4], const uint32_t b[2]) {
    asm volatile(
        "mma.sync.aligned.m16n8k8.row.col.f32.tf32.tf32.f32 "
        "{%0,%1,%2,%3}, {%4,%5,%6,%7}, {%8,%9}, {%0,%1,%2,%3};"
        : "+f"(c[0]), "+f"(c[1]), "+f"(c[2]), "+f"(c[3])
        : "r"(a[0]), "r"(a[1]), "r"(a[2]), "r"(a[3]), "r"(b[0]), "r"(b[1]));
}
__device__ __forceinline__ uint32_t smem_u32(const void* p) {
    uint32_t a;
    asm("{ .reg .u64 t; cvta.to.shared.u64 t, %1; cvt.u32.u64 %0, t; }" : "=r"(a) : "l"(p));
    return a;
}
__device__ __forceinline__ void cp_async16(uint32_t dst, const void* src) {
    asm volatile("cp.async.cg.shared.global [%0], [%1], 16;" :: "r"(dst), "l"(src) : "memory");
}
// interleaved dual warp-sum (two independent shuffle chains)
__device__ __forceinline__ void warp_sum2(float& s1, float& s2) {
#pragma unroll
    for (int o = 16; o; o >>= 1) {
        s1 += __shfl_xor_sync(0xffffffffu, s1, o);
        s2 += __shfl_xor_sync(0xffffffffu, s2, o);
    }
}

// ---------------------------------------------------------------------------
// K0: init g_flag = 0, g_invrank = -1
// ---------------------------------------------------------------------------
__global__ void __launch_bounds__(256) zero_misc_kernel()
{
    int t = blockIdx.x * 256 + threadIdx.x;
    if (t < MW_CNT / 16)
        reinterpret_cast<uint4*>(g_flag)[t] = make_uint4(0u, 0u, 0u, 0u);
    int u = t - MW_CNT / 16;
    if (u >= 0 && u < N_TOK / 4)
        reinterpret_cast<int4*>(g_invrank)[u] = make_int4(-1, -1, -1, -1);
}

// ---------------------------------------------------------------------------
// K1: flag + rank + inverse-rank maps
// ---------------------------------------------------------------------------
__global__ void __launch_bounds__(256) set_flags_kernel(
    const int* __restrict__ asy, const int* __restrict__ blk, const int* __restrict__ iw)
{
    int t = blockIdx.x * 256 + threadIdx.x;
    if (t < A_CNT) {
        int g = asy[t];
        int wrow = iw[g >> 6] * 64 + (g & 63);
        g_flag[g] = 1;
        g_rank[g] = t;
        g_asyrow[t] = wrow;
        g_invrank[wrow] = t;
    } else if (t < A_CNT + BL_CNT) {
        g_flag[blk[t - A_CNT]] = 2;
    }
}

// ---------------------------------------------------------------------------
// K2: X = LN(x) -> out; fused second LN for asy-targeted rows -> g_xa
// ---------------------------------------------------------------------------
__global__ void __launch_bounds__(256) ln_kernel(
    const float* __restrict__ x, const float* __restrict__ w,
    const float* __restrict__ b, float* __restrict__ out)
{
    int row  = (int)((blockIdx.x * 256u + threadIdx.x) >> 5);
    int lane = threadIdx.x & 31;
    if (row >= N_TOK) return;
    float4 v = reinterpret_cast<const float4*>(x + (size_t)row * C_DIM)[lane];
    float s1 = v.x + v.y + v.z + v.w;
    float s2 = v.x*v.x + v.y*v.y + v.z*v.z + v.w*v.w;
    warp_sum2(s1, s2);
    float m = s1 * (1.0f / C_DIM);
    float var = s2 * (1.0f / C_DIM) - m * m;
    float inv = rsqrtf(var + EPS_LN);
    float4 wv = reinterpret_cast<const float4*>(w)[lane];
    float4 bv = reinterpret_cast<const float4*>(b)[lane];
    float4 r;
    r.x = (v.x - m) * inv * wv.x + bv.x; r.y = (v.y - m) * inv * wv.y + bv.y;
    r.z = (v.z - m) * inv * wv.z + bv.z; r.w = (v.w - m) * inv * wv.w + bv.w;
    reinterpret_cast<float4*>(out + (size_t)row * C_DIM)[lane] = r;

    int ir = g_invrank[row];
    if (ir >= 0) {
        float t1 = r.x + r.y + r.z + r.w;
        float t2 = r.x*r.x + r.y*r.y + r.z*r.z + r.w*r.w;
        warp_sum2(t1, t2);
        float m2 = t1 * (1.0f / C_DIM);
        float var2 = t2 * (1.0f / C_DIM) - m2 * m2;
        float inv2 = rsqrtf(var2 + EPS_LN);
        float4 o;
        o.x = (r.x - m2) * inv2 * wv.x + bv.x; o.y = (r.y - m2) * inv2 * wv.y + bv.y;
        o.z = (r.z - m2) * inv2 * wv.z + bv.z; o.w = (r.w - m2) * inv2 * wv.w + bv.w;
        reinterpret_cast<float4*>(g_xa + (size_t)ir * C_DIM)[lane] = o;
    }
}

// ---------------------------------------------------------------------------
// K3: gather partition-order rows -> g_xp_bf (bf16) + meta arrays
// ---------------------------------------------------------------------------
__global__ void __launch_bounds__(256) gather_kernel(
    const float* __restrict__ X, const int* __restrict__ ipart, const int* __restrict__ iw)
{
    int i    = (int)((blockIdx.x * 256u + threadIdx.x) >> 5);
    int lane = threadIdx.x & 31;
    if (i >= MW_CNT) return;
    int g = ipart[i];
    int f = g_flag[g];
    int wrow = iw[g >> 6] * 64 + (g & 63);
    int rnk = (f == 1) ? g_rank[g] : 0;
    if (lane == 0) { g_mflag[i] = (unsigned char)f; g_mrow[i] = wrow; g_mrank[i] = rnk; }
    const float* srcp = (f == 1) ? (g_xa + (size_t)rnk * C_DIM)
                                 : (X + (size_t)wrow * C_DIM);
    float4 v = reinterpret_cast<const float4*>(srcp)[lane];
    __nv_bfloat162 b0 = __floats2bfloat162_rn(v.x, v.y);
    __nv_bfloat162 b1 = __floats2bfloat162_rn(v.z, v.w);
    uint2 u;
    u.x = *reinterpret_cast<uint32_t*>(&b0);
    u.y = *reinterpret_cast<uint32_t*>(&b1);
    *reinterpret_cast<uint2*>(g_xp_bf + (size_t)i * C_DIM + lane * 4) = u;
}

// ---------------------------------------------------------------------------
// GEMM v4: tf32 warp-MMA, 128x128 block tile, bf16 A (reg-staged pipelined
// LDG) + fp32 W (cp.async double-buffered).  8 warps 4x2, warp tile 32x64.
//   EPI 0: +bias -> out            EPI 1: +bias, scatter via g_m* meta
//   EPI 2: +bias, gelu -> out      EPI 3: +bias, g_y + evec*acc -> out[g_asyrow]
//   OBF  : write output as bf16 (EPI 0/2)
// ---------------------------------------------------------------------------
#define AS_STRIDE 36
#define BS_STRIDE 136
#define GEMM_ASZ (128 * AS_STRIDE)
#define GEMM_BSZ (32 * BS_STRIDE)
#define GEMM_SMEM_BYTES ((2 * GEMM_ASZ + 2 * GEMM_BSZ) * 4)

template<int NTOT, int KTOT, int EPI, int OBF>
__global__ void __launch_bounds__(256) gemm4_kernel(
    const __nv_bfloat16* __restrict__ Ab, const float* __restrict__ W,
    const float* __restrict__ bias, void* __restrict__ outv,
    const float* __restrict__ evec)
{
    extern __shared__ float smf[];
    float* As = smf;                       // 2 stages of 128x32 (stride 36)
    float* Bs = smf + 2 * GEMM_ASZ;        // 2 stages of 32x128 (stride 136)

    int tid  = threadIdx.x;
    int lane = tid & 31;
    int wid  = tid >> 5;
    int wr   = wid >> 1;
    int wc   = wid & 1;
    int g    = lane >> 2;
    int tg   = lane & 3;
    size_t m0 = (size_t)blockIdx.x * 128;
    int n0 = blockIdx.y * 128;
    constexpr int NC = KTOT / 32;

    uint32_t bs_u = smem_u32(Bs);

    uint4 areg[2];
    auto ldgA = [&](int kc) {
#pragma unroll
        for (int t = 0; t < 2; t++) {
            int idx = tid + t * 256;
            int r = idx >> 2, cc = (idx & 3) * 8;
            areg[t] = *reinterpret_cast<const uint4*>(
                Ab + (m0 + r) * KTOT + kc * 32 + cc);
        }
    };
    auto stsA = [&](int s) {
#pragma unroll
        for (int t = 0; t < 2; t++) {
            int idx = tid + t * 256;
            int r = idx >> 2, cc = (idx & 3) * 8;
            __nv_bfloat162* p = reinterpret_cast<__nv_bfloat162*>(&areg[t]);
            float2 f0 = __bfloat1622float2(p[0]);
            float2 f1 = __bfloat1622float2(p[1]);
            float2 f2 = __bfloat1622float2(p[2]);
            float2 f3 = __bfloat1622float2(p[3]);
            float* d = &As[s * GEMM_ASZ + r * AS_STRIDE + cc];
            *reinterpret_cast<float4*>(d)     = make_float4(f0.x, f0.y, f1.x, f1.y);
            *reinterpret_cast<float4*>(d + 4) = make_float4(f2.x, f2.y, f3.x, f3.y);
        }
    };
    auto loadB = [&](int kc, int s) {
#pragma unroll
        for (int t = 0; t < 4; t++) {
            int idx = tid + t * 256;
            int r = idx >> 5, cc = (idx & 31) * 4;
            cp_async16(bs_u + (uint32_t)(s * GEMM_BSZ + r * BS_STRIDE + cc) * 4,
                       W + (size_t)(kc * 32 + r) * NTOT + n0 + cc);
        }
        asm volatile("cp.async.commit_group;" ::: "memory");
    };

    float c[2][8][4];
#pragma unroll
    for (int i = 0; i < 2; i++)
#pragma unroll
        for (int j = 0; j < 8; j++)
#pragma unroll
            for (int q = 0; q < 4; q++) c[i][j][q] = 0.0f;

    ldgA(0);
    loadB(0, 0);
    stsA(0);
    for (int kc = 0; kc < NC; kc++) {
        int s = kc & 1;
        if (kc + 1 < NC) {
            loadB(kc + 1, s ^ 1);
            asm volatile("cp.async.wait_group 1;" ::: "memory");
        } else {
            asm volatile("cp.async.wait_group 0;" ::: "memory");
        }
        __syncthreads();
        if (kc + 1 < NC) ldgA(kc + 1);

        const float* Ap = As + s * GEMM_ASZ;
        const float* Bp = Bs + s * GEMM_BSZ;
#pragma unroll
        for (int kb = 0; kb < 4; kb++) {
            uint32_t a[2][4], b[8][2];
#pragma unroll
            for (int i = 0; i < 2; i++) {
                int row = wr * 32 + i * 16 + g;
                a[i][0] = __float_as_uint(Ap[row * AS_STRIDE + kb * 8 + tg]);
                a[i][1] = __float_as_uint(Ap[(row + 8) * AS_STRIDE + kb * 8 + tg]);
                a[i][2] = __float_as_uint(Ap[row * AS_STRIDE + kb * 8 + tg + 4]);
                a[i][3] = __float_as_uint(Ap[(row + 8) * AS_STRIDE + kb * 8 + tg + 4]);
            }
#pragma unroll
            for (int j = 0; j < 8; j++) {
                int n = wc * 64 + j * 8 + g;
                b[j][0] = __float_as_uint(Bp[(kb * 8 + tg) * BS_STRIDE + n]);
                b[j][1] = __float_as_uint(Bp[(kb * 8 + tg + 4) * BS_STRIDE + n]);
            }
#pragma unroll
            for (int i = 0; i < 2; i++)
#pragma unroll
                for (int j = 0; j < 8; j++)
                    mma_tf32(c[i][j], a[i], b[j]);
        }
        __syncthreads();
        if (kc + 1 < NC) stsA(s ^ 1);
    }

    // ---- epilogue ----
#pragma unroll
    for (int i = 0; i < 2; i++) {
#pragma unroll
        for (int half = 0; half < 2; half++) {
            size_t grow = m0 + wr * 32 + i * 16 + g + half * 8;
            float* dstf = nullptr;
            int f = 0;
            if constexpr (EPI == 1) {
                f = g_mflag[grow];
                dstf = (f == 1) ? (g_att + (size_t)g_mrank[grow] * C_DIM)
                                : ((float*)outv + (size_t)g_mrow[grow] * C_DIM);
            } else if constexpr (EPI == 3) {
                dstf = (float*)outv + (size_t)g_asyrow[grow] * C_DIM;
            }
#pragma unroll
            for (int j = 0; j < 8; j++) {
                int colg = n0 + wc * 64 + j * 8 + tg * 2;
                float v0 = c[i][j][half * 2]     + __ldg(&bias[colg]);
                float v1 = c[i][j][half * 2 + 1] + __ldg(&bias[colg + 1]);
                if constexpr (EPI == 2) {
                    v0 = 0.5f * v0 * (1.0f + erff(v0 * 0.7071067811865476f));
                    v1 = 0.5f * v1 * (1.0f + erff(v1 * 0.7071067811865476f));
                }
                if constexpr (EPI == 3) {
                    v0 = g_y[grow * C_DIM + colg]     + __ldg(&evec[colg]) * v0;
                    v1 = g_y[grow * C_DIM + colg + 1] + __ldg(&evec[colg + 1]) * v1;
                }
                if constexpr (EPI == 1) {
                    if (f != 2)
                        *reinterpret_cast<float2*>(dstf + colg) = make_float2(v0, v1);
                } else if constexpr (EPI == 3) {
                    *reinterpret_cast<float2*>(dstf + colg) = make_float2(v0, v1);
                } else if constexpr (OBF) {
                    *reinterpret_cast<__nv_bfloat162*>(
                        (__nv_bfloat16*)outv + grow * NTOT + colg) =
                        __floats2bfloat162_rn(v0, v1);
                } else {
                    *reinterpret_cast<float2*>((float*)outv + grow * NTOT + colg) =
                        make_float2(v0, v1);
                }
            }
        }
    }
}

// ---------------------------------------------------------------------------
// K5: tensor-core attention per partition. g_qkv_bf (64x384) -> g_o_bf (64x128).
// ---------------------------------------------------------------------------
#define QS3 388
#define SS3 66
#define ATTN3_SMEM_BYTES ((64 * QS3 + 4 * 64 * SS3) * 4 + 256)

__global__ void __launch_bounds__(256, 1) attn3_kernel(
    const __nv_bfloat16* __restrict__ gqkv, __nv_bfloat16* __restrict__ go)
{
    extern __shared__ float sm[];
    float* qsm = sm;                         // 64 x QS3
    float* ssm = sm + 64 * QS3;              // 4 heads x 64 x SS3
    int* kfl   = (int*)(ssm + 4 * 64 * SS3); // 64

    int m   = blockIdx.x;
    int tid = threadIdx.x;
    if (tid < 64) kfl[tid] = g_mflag[m * 64 + tid];

    const uint4* src = reinterpret_cast<const uint4*>(gqkv + (size_t)m * 64 * 384);
    for (int i = tid; i < 3072; i += 256) {
        int r = i / 48, c8 = (i - r * 48) * 8;
        uint4 u = src[i];
        float2 f0 = __bfloat1622float2(*reinterpret_cast<__nv_bfloat162*>(&u.x));
        float2 f1 = __bfloat1622float2(*reinterpret_cast<__nv_bfloat162*>(&u.y));
        float2 f2 = __bfloat1622float2(*reinterpret_cast<__nv_bfloat162*>(&u.z));
        float2 f3 = __bfloat1622float2(*reinterpret_cast<__nv_bfloat162*>(&u.w));
        float* d = &qsm[r * QS3 + c8];
        d[0] = f0.x; d[1] = f0.y; d[2] = f1.x; d[3] = f1.y;
        d[4] = f2.x; d[5] = f2.y; d[6] = f3.x; d[7] = f3.y;
    }
    __syncthreads();

    int wid = tid >> 5, lane = tid & 31;
    int g = lane >> 2, tg = lane & 3;
    int h = wid >> 1;
    int rbase = (wid & 1) * 32;
    int bq = h * 96, bk = bq + 32, bv = bq + 64;
    float* ssh = ssm + h * 64 * SS3;
    const float scale = 0.17677669529663687f;

    // ---- S = Q K^T ----
    float c[2][8][4];
#pragma unroll
    for (int i = 0; i < 2; i++)
#pragma unroll
        for (int j = 0; j < 8; j++)
#pragma unroll
            for (int q = 0; q < 4; q++) c[i][j][q] = 0.0f;

#pragma unroll
    for (int kt = 0; kt < 4; kt++) {
        uint32_t a[2][4], b[8][2];
#pragma unroll
        for (int i = 0; i < 2; i++) {
            int row = rbase + i * 16 + g;
            a[i][0] = __float_as_uint(qsm[row * QS3 + bq + kt * 8 + tg]);
            a[i][1] = __float_as_uint(qsm[(row + 8) * QS3 + bq + kt * 8 + tg]);
            a[i][2] = __float_as_uint(qsm[row * QS3 + bq + kt * 8 + tg + 4]);
            a[i][3] = __float_as_uint(qsm[(row + 8) * QS3 + bq + kt * 8 + tg + 4]);
        }
#pragma unroll
        for (int j = 0; j < 8; j++) {
            int n = j * 8 + g;
            b[j][0] = __float_as_uint(qsm[n * QS3 + bk + kt * 8 + tg]);
            b[j][1] = __float_as_uint(qsm[n * QS3 + bk + kt * 8 + tg + 4]);
        }
#pragma unroll
        for (int i = 0; i < 2; i++)
#pragma unroll
            for (int j = 0; j < 8; j++)
                mma_tf32(c[i][j], a[i], b[j]);
    }

    // ---- mask bits ----
    unsigned mask = 0;
#pragma unroll
    for (int j = 0; j < 8; j++)
#pragma unroll
        for (int q = 0; q < 2; q++)
            if (kfl[j * 8 + 2 * tg + q] == 2) mask |= 1u << (j * 2 + q);

    // ---- register softmax (quad shuffles) ----
#pragma unroll
    for (int i = 0; i < 2; i++) {
#pragma unroll
        for (int sel = 0; sel < 2; sel++) {
            float mx = -1e30f;
#pragma unroll
            for (int j = 0; j < 8; j++)
#pragma unroll
                for (int q = 0; q < 2; q++) {
                    float v = c[i][j][sel * 2 + q] * scale;
                    if (mask & (1u << (j * 2 + q))) v = -10000.0f;
                    c[i][j][sel * 2 + q] = v;
                    mx = fmaxf(mx, v);
                }
            mx = fmaxf(mx, __shfl_xor_sync(0xffffffffu, mx, 1));
            mx = fmaxf(mx, __shfl_xor_sync(0xffffffffu, mx, 2));
            float s = 0.0f;
#pragma unroll
            for (int j = 0; j < 8; j++)
#pragma unroll
                for (int q = 0; q < 2; q++) {
                    float e = __expf(c[i][j][sel * 2 + q] - mx);
                    c[i][j][sel * 2 + q] = e;
                    s += e;
                }
            s += __shfl_xor_sync(0xffffffffu, s, 1);
            s += __shfl_xor_sync(0xffffffffu, s, 2);
            float rinv = 1.0f / s;
            int row = rbase + i * 16 + g + sel * 8;
#pragma unroll
            for (int j = 0; j < 8; j++)
#pragma unroll
                for (int q = 0; q < 2; q++)
                    ssh[row * SS3 + j * 8 + 2 * tg + q] = c[i][j][sel * 2 + q] * rinv;
        }
    }
    __syncwarp();

    // ---- O = P @ V ----
    float o[2][4][4];
#pragma unroll
    for (int i = 0; i < 2; i++)
#pragma unroll
        for (int j = 0; j < 4; j++)
#pragma unroll
            for (int q = 0; q < 4; q++) o[i][j][q] = 0.0f;

#pragma unroll
    for (int kt = 0; kt < 8; kt++) {
        uint32_t a[2][4], b[4][2];
#pragma unroll
        for (int i = 0; i < 2; i++) {
            int row = rbase + i * 16 + g;
            a[i][0] = __float_as_uint(ssh[row * SS3 + kt * 8 + tg]);
            a[i][1] = __float_as_uint(ssh[(row + 8) * SS3 + kt * 8 + tg]);
            a[i][2] = __float_as_uint(ssh[row * SS3 + kt * 8 + tg + 4]);
            a[i][3] = __float_as_uint(ssh[(row + 8) * SS3 + kt * 8 + tg + 4]);
        }
#pragma unroll
        for (int j = 0; j < 4; j++) {
            int n = j * 8 + g;
            b[j][0] = __float_as_uint(qsm[(kt * 8 + tg) * QS3 + bv + n]);
            b[j][1] = __float_as_uint(qsm[(kt * 8 + tg + 4) * QS3 + bv + n]);
        }
#pragma unroll
        for (int i = 0; i < 2; i++)
#pragma unroll
            for (int j = 0; j < 4; j++)
                mma_tf32(o[i][j], a[i], b[j]);
    }

#pragma unroll
    for (int i = 0; i < 2; i++)
#pragma unroll
        for (int j = 0; j < 4; j++) {
            size_t row = (size_t)(m * 64 + rbase + i * 16 + g);
            int col = h * 32 + j * 8 + 2 * tg;
            *reinterpret_cast<__nv_bfloat162*>(&go[row * C_DIM + col]) =
                __floats2bfloat162_rn(o[i][j][0], o[i][j][1]);
            *reinterpret_cast<__nv_bfloat162*>(&go[(row + 8) * C_DIM + col]) =
                __floats2bfloat162_rn(o[i][j][2], o[i][j][3]);
        }
}

// ---------------------------------------------------------------------------
// K7: y = xa + g1*att -> g_y (fp32) ; LN2(y) -> g_yn_bf (bf16)
// ---------------------------------------------------------------------------
__global__ void __launch_bounds__(256) ybuild_kernel(
    const float* __restrict__ g1,
    const float* __restrict__ ln2w, const float* __restrict__ ln2b)
{
    int r    = (int)((blockIdx.x * 256u + threadIdx.x) >> 5);
    int lane = threadIdx.x & 31;
    if (r >= A_CNT) return;
    float4 a = reinterpret_cast<const float4*>(g_xa + (size_t)r * C_DIM)[lane];
    float4 t = reinterpret_cast<const float4*>(g_att + (size_t)r * C_DIM)[lane];
    float4 gv = reinterpret_cast<const float4*>(g1)[lane];
    float4 y;
    y.x = a.x + gv.x * t.x; y.y = a.y + gv.y * t.y;
    y.z = a.z + gv.z * t.z; y.w = a.w + gv.w * t.w;
    reinterpret_cast<float4*>(g_y + (size_t)r * C_DIM)[lane] = y;
    float s1 = y.x + y.y + y.z + y.w;
    float s2 = y.x*y.x + y.y*y.y + y.z*y.z + y.w*y.w;
    warp_sum2(s1, s2);
    float m = s1 * (1.0f / C_DIM);
    float var = s2 * (1.0f / C_DIM) - m * m;
    float inv = rsqrtf(var + EPS_LN);
    float4 wv = reinterpret_cast<const float4*>(ln2w)[lane];
    float4 bv = reinterpret_cast<const float4*>(ln2b)[lane];
    __nv_bfloat162 b0 = __floats2bfloat162_rn(
        (y.x - m) * inv * wv.x + bv.x, (y.y - m) * inv * wv.y + bv.y);
    __nv_bfloat162 b1 = __floats2bfloat162_rn(
        (y.z - m) * inv * wv.z + bv.z, (y.w - m) * inv * wv.w + bv.w);
    uint2 u;
    u.x = *reinterpret_cast<uint32_t*>(&b0);
    u.y = *reinterpret_cast<uint32_t*>(&b1);
    *reinterpret_cast<uint2*>(g_yn_bf + (size_t)r * C_DIM + lane * 4) = u;
}

// ---------------------------------------------------------------------------
extern "C" void kernel_launch(void* const* d_in, const int* in_sizes, int n_in,
                              void* d_out, int out_size)
{
    int base = 7;
    if (n_in == 19) base = 5;

    const float* x      = (const float*)d_in[0];
    const int*   iw     = (const int*)d_in[1];
    const int*   ipart  = (const int*)d_in[2];
    const int*   asy    = (const int*)d_in[3];
    const int*   blk    = (const int*)d_in[4];
    const float* ln1w   = (const float*)d_in[base + 0];
    const float* ln1b   = (const float*)d_in[base + 1];
    const float* qkvw   = (const float*)d_in[base + 2];
    const float* qkvb   = (const float*)d_in[base + 3];
    const float* projw  = (const float*)d_in[base + 4];
    const float* projb  = (const float*)d_in[base + 5];
    const float* g1     = (const float*)d_in[base + 6];
    const float* ln2w   = (const float*)d_in[base + 7];
    const float* ln2b   = (const float*)d_in[base + 8];
    const float* w1     = (const float*)d_in[base + 9];
    const float* b1     = (const float*)d_in[base + 10];
    const float* w2     = (const float*)d_in[base + 11];
    const float* b2     = (const float*)d_in[base + 12];
    const float* g2     = (const float*)d_in[base + 13];
    float* out = (float*)d_out;

    __nv_bfloat16 *p_xp, *p_qkv, *p_o, *p_yn, *p_h;
    cudaGetSymbolAddress((void**)&p_xp, g_xp_bf);
    cudaGetSymbolAddress((void**)&p_qkv, g_qkv_bf);
    cudaGetSymbolAddress((void**)&p_o, g_o_bf);
    cudaGetSymbolAddress((void**)&p_yn, g_yn_bf);
    cudaGetSymbolAddress((void**)&p_h, g_h_bf);

    cudaFuncSetAttribute(gemm4_kernel<384, 128, 0, 1>,
                         cudaFuncAttributeMaxDynamicSharedMemorySize, GEMM_SMEM_BYTES);
    cudaFuncSetAttribute(gemm4_kernel<128, 128, 1, 0>,
                         cudaFuncAttributeMaxDynamicSharedMemorySize, GEMM_SMEM_BYTES);
    cudaFuncSetAttribute(gemm4_kernel<512, 128, 2, 1>,
                         cudaFuncAttributeMaxDynamicSharedMemorySize, GEMM_SMEM_BYTES);
    cudaFuncSetAttribute(gemm4_kernel<128, 512, 3, 0>,
                         cudaFuncAttributeMaxDynamicSharedMemorySize, GEMM_SMEM_BYTES);
    cudaFuncSetAttribute(attn3_kernel,
                         cudaFuncAttributeMaxDynamicSharedMemorySize, ATTN3_SMEM_BYTES);

    // 0-1. init + flag/rank maps
    zero_misc_kernel<<<(MW_CNT / 16 + N_TOK / 4 + 255) / 256, 256>>>();
    set_flags_kernel<<<(A_CNT + BL_CNT + 255) / 256, 256>>>(asy, blk, iw);
    // 2. X = LN(x) (+ fused double-LN for asy rows)
    ln_kernel<<<N_TOK / 8, 256>>>(x, ln1w, ln1b, out);
    // 3. gather partition-order rows (bf16) + meta
    gather_kernel<<<MW_CNT / 8, 256>>>(out, ipart, iw);
    // 4. QKV GEMM -> bf16
    gemm4_kernel<384, 128, 0, 1><<<dim3(MW_CNT / 128, 3), 256, GEMM_SMEM_BYTES>>>(
        p_xp, qkvw, qkvb, p_qkv, nullptr);
    // 5. attention (tensor cores) -> bf16
    attn3_kernel<<<M_PART, 256, ATTN3_SMEM_BYTES>>>(p_qkv, p_o);
    // 6. proj GEMM + scatter (fp32 out)
    gemm4_kernel<128, 128, 1, 0><<<dim3(MW_CNT / 128, 1), 256, GEMM_SMEM_BYTES>>>(
        p_o, projw, projb, out, nullptr);
    // 7. y build + LN2 (bf16 yn)
    ybuild_kernel<<<A_CNT / 8, 256>>>(g1, ln2w, ln2b);
    // 8. MLP GEMM1 + gelu -> bf16
    gemm4_kernel<512, 128, 2, 1><<<dim3(A_CNT / 128, 4), 256, GEMM_SMEM_BYTES>>>(
        p_yn, w1, b1, p_h, nullptr);
    // 9. MLP GEMM2 + residual + scatter (fp32 out)
    gemm4_kernel<128, 512, 3, 0><<<dim3(A_CNT / 128, 1), 256, GEMM_SMEM_BYTES>>>(
        p_h, w2, b2, out, g2);
}

// round 8
// speedup vs baseline: 1.0831x; 1.0756x over previous
#include <cuda_runtime.h>
#include <cuda_bf16.h>
#include <math.h>
#include <stdint.h>

// Problem constants
#define N_TOK   524288
#define N_WIN   8192      // token count (domain of g_winv)
#define P_TOK   64
#define C_DIM   128
#define M_PART  4096      // number of windows == number of partitions
#define MW_CNT  262144
#define A_CNT   131072
#define BL_CNT  65536
#define EPS_LN  1e-6f

// ---------------------------------------------------------------------------
// Scratch (device globals — allocation-free rule)
// ---------------------------------------------------------------------------
__device__ float g_xa[(size_t)A_CNT * C_DIM];            // double-LN asy rows (rank order)
__device__ float g_att[(size_t)A_CNT * C_DIM];           // proj output for asy rows
__device__ float g_y[(size_t)A_CNT * C_DIM];             // MLP residual input
__device__ __nv_bfloat16 g_xp_bf[(size_t)MW_CNT * C_DIM];  // gathered attn input (bf16)
__device__ __nv_bfloat16 g_qkv_bf[(size_t)MW_CNT * 384];   // QKV output (bf16)
__device__ __nv_bfloat16 g_o_bf[(size_t)MW_CNT * C_DIM];   // attention output (bf16)
__device__ __nv_bfloat16 g_yn_bf[(size_t)A_CNT * C_DIM];   // LN2(y) (bf16)
__device__ __nv_bfloat16 g_h_bf[(size_t)A_CNT * 512];      // MLP hidden (bf16)
__device__ unsigned char g_flag[MW_CNT];                 // 0 none, 1 asy, 2 blocked
__device__ int g_rank[MW_CNT];
__device__ int g_ipos[MW_CNT];                           // window pos -> partition slot
__device__ int g_winv[N_WIN];                            // token idx -> window idx (-1)
__device__ int g_asyrow[A_CNT];                          // window row of asy[i]
__device__ unsigned char g_mflag[MW_CNT];                // partition-order meta
__device__ int g_mrow[MW_CNT];
__device__ int g_mrank[MW_CNT];

// ---------------------------------------------------------------------------
// helpers
// ---------------------------------------------------------------------------
__device__ __forceinline__ void mma_tf32(float c[4], const uint32_t a[4], const uint32_t b[2]) {
    asm volatile(
        "mma.sync.aligned.m16n8k8.row.col.f32.tf32.tf32.f32 "
        "{%0,%1,%2,%3}, {%4,%5,%6,%7}, {%8,%9}, {%0,%1,%2,%3};"
        : "+f"(c[0]), "+f"(c[1]), "+f"(c[2]), "+f"(c[3])
        : "r"(a[0]), "r"(a[1]), "r"(a[2]), "r"(a[3]), "r"(b[0]), "r"(b[1]));
}
__device__ __forceinline__ uint32_t smem_u32(const void* p) {
    uint32_t a;
    asm("{ .reg .u64 t; cvta.to.shared.u64 t, %1; cvt.u32.u64 %0, t; }" : "=r"(a) : "l"(p));
    return a;
}
__device__ __forceinline__ void cp_async16(uint32_t dst, const void* src) {
    asm volatile("cp.async.cg.shared.global [%0], [%1], 16;" :: "r"(dst), "l"(src) : "memory");
}
__device__ __forceinline__ void warp_sum2(float& s1, float& s2) {
#pragma unroll
    for (int o = 16; o; o >>= 1) {
        s1 += __shfl_xor_sync(0xffffffffu, s1, o);
        s2 += __shfl_xor_sync(0xffffffffu, s2, o);
    }
}
__device__ __forceinline__ void warp_sum4(float& a1, float& a2, float& b1, float& b2) {
#pragma unroll
    for (int o = 16; o; o >>= 1) {
        a1 += __shfl_xor_sync(0xffffffffu, a1, o);
        a2 += __shfl_xor_sync(0xffffffffu, a2, o);
        b1 += __shfl_xor_sync(0xffffffffu, b1, o);
        b2 += __shfl_xor_sync(0xffffffffu, b2, o);
    }
}

// ---------------------------------------------------------------------------
// K0: init g_flag = 0, g_winv = -1
// ---------------------------------------------------------------------------
__global__ void __launch_bounds__(256) zero_misc_kernel()
{
    int t = blockIdx.x * 256 + threadIdx.x;
    if (t < MW_CNT / 16)
        reinterpret_cast<uint4*>(g_flag)[t] = make_uint4(0u, 0u, 0u, 0u);
    int u = t - MW_CNT / 16;
    if (u >= 0 && u < N_WIN / 4)
        reinterpret_cast<int4*>(g_winv)[u] = make_int4(-1, -1, -1, -1);
}

// ---------------------------------------------------------------------------
// K1: all index maps
// ---------------------------------------------------------------------------
__global__ void __launch_bounds__(256) set_maps_kernel(
    const int* __restrict__ asy, const int* __restrict__ blk,
    const int* __restrict__ iw, const int* __restrict__ ipart)
{
    int t = blockIdx.x * 256 + threadIdx.x;
    if (t < MW_CNT) g_ipos[ipart[t]] = t;
    if (t < A_CNT) {
        int g = asy[t];
        g_flag[g] = 1;
        g_rank[g] = t;
        g_asyrow[t] = iw[g >> 6] * 64 + (g & 63);
    } else if (t < A_CNT + BL_CNT) {
        g_flag[blk[t - A_CNT]] = 2;
    }
    if (t < M_PART) g_winv[iw[t]] = t;   // FIXED: iw has M_PART entries, not N_WIN
}

// ---------------------------------------------------------------------------
// K2: partition-order meta
// ---------------------------------------------------------------------------
__global__ void __launch_bounds__(256) meta_kernel(
    const int* __restrict__ ipart, const int* __restrict__ iw)
{
    int i = blockIdx.x * 256 + threadIdx.x;
    if (i >= MW_CNT) return;
    int g = ipart[i];
    int f = g_flag[g];
    g_mflag[i] = (unsigned char)f;
    g_mrow[i]  = iw[g >> 6] * 64 + (g & 63);
    g_mrank[i] = (f == 1) ? g_rank[g] : 0;
}

// ---------------------------------------------------------------------------
// K3: fused LN + scatter. 2 rows per warp.
//   X = LN(x): written to out ONLY for non-window or blocked rows.
//   Window rows: scatter bf16 X (or double-LN xa for asy) into g_xp_bf[ipos];
//   asy rows additionally write fp32 xa -> g_xa[rank].
// ---------------------------------------------------------------------------
__global__ void __launch_bounds__(256) ln_kernel(
    const float* __restrict__ x, const float* __restrict__ w,
    const float* __restrict__ b, float* __restrict__ out)
{
    int wglob = blockIdx.x * 8 + (threadIdx.x >> 5);
    int lane  = threadIdx.x & 31;
    int r0 = wglob * 2;
    int r1 = r0 + 1;

    float4 v0 = reinterpret_cast<const float4*>(x + (size_t)r0 * C_DIM)[lane];
    float4 v1 = reinterpret_cast<const float4*>(x + (size_t)r1 * C_DIM)[lane];
    float4 wv = reinterpret_cast<const float4*>(w)[lane];
    float4 bv = reinterpret_cast<const float4*>(b)[lane];

    float a1 = v0.x + v0.y + v0.z + v0.w;
    float a2 = v0.x*v0.x + v0.y*v0.y + v0.z*v0.z + v0.w*v0.w;
    float c1 = v1.x + v1.y + v1.z + v1.w;
    float c2 = v1.x*v1.x + v1.y*v1.y + v1.z*v1.z + v1.w*v1.w;
    warp_sum4(a1, a2, c1, c2);

#pragma unroll
    for (int rr = 0; rr < 2; rr++) {
        int row = rr ? r1 : r0;
        float4 v = rr ? v1 : v0;
        float s1 = rr ? c1 : a1;
        float s2 = rr ? c2 : a2;
        float m = s1 * (1.0f / C_DIM);
        float var = s2 * (1.0f / C_DIM) - m * m;
        float inv = rsqrtf(var + EPS_LN);
        float4 r;
        r.x = (v.x - m) * inv * wv.x + bv.x; r.y = (v.y - m) * inv * wv.y + bv.y;
        r.z = (v.z - m) * inv * wv.z + bv.z; r.w = (v.w - m) * inv * wv.w + bv.w;

        int n = row >> 6, p = row & 63;
        int widx = g_winv[n];
        if (widx < 0) {
            reinterpret_cast<float4*>(out + (size_t)row * C_DIM)[lane] = r;
        } else {
            int g = widx * 64 + p;
            int f = g_flag[g];
            int ipos = g_ipos[g];
            float4 val = r;
            if (f == 2) {
                reinterpret_cast<float4*>(out + (size_t)row * C_DIM)[lane] = r;
            } else if (f == 1) {
                float t1 = r.x + r.y + r.z + r.w;
                float t2 = r.x*r.x + r.y*r.y + r.z*r.z + r.w*r.w;
                warp_sum2(t1, t2);
                float m2 = t1 * (1.0f / C_DIM);
                float var2 = t2 * (1.0f / C_DIM) - m2 * m2;
                float inv2 = rsqrtf(var2 + EPS_LN);
                val.x = (r.x - m2) * inv2 * wv.x + bv.x;
                val.y = (r.y - m2) * inv2 * wv.y + bv.y;
                val.z = (r.z - m2) * inv2 * wv.z + bv.z;
                val.w = (r.w - m2) * inv2 * wv.w + bv.w;
                reinterpret_cast<float4*>(g_xa + (size_t)g_rank[g] * C_DIM)[lane] = val;
            }
            __nv_bfloat162 b0 = __floats2bfloat162_rn(val.x, val.y);
            __nv_bfloat162 b1 = __floats2bfloat162_rn(val.z, val.w);
            uint2 u;
            u.x = *reinterpret_cast<uint32_t*>(&b0);
            u.y = *reinterpret_cast<uint32_t*>(&b1);
            *reinterpret_cast<uint2*>(g_xp_bf + (size_t)ipos * C_DIM + lane * 4) = u;
        }
    }
}

// ---------------------------------------------------------------------------
// GEMM5: A-resident tf32 warp-MMA. Block = 128 rows, full K=128 A panel in
// SMEM (fp32), loops NTOT/128 n-chunks with cp.async double-buffered B.
//   EPI 0: +bias -> bf16 out    EPI 2: +bias, gelu -> bf16 out
// ---------------------------------------------------------------------------
#define A5_STRIDE 132
#define B5_STRIDE 136
#define B5_SZ (32 * B5_STRIDE)
#define GEMM5_SMEM_BYTES ((128 * A5_STRIDE + 2 * B5_SZ) * 4)

template<int NTOT, int EPI>
__global__ void __launch_bounds__(256) gemm5_kernel(
    const __nv_bfloat16* __restrict__ Ab, const float* __restrict__ W,
    const float* __restrict__ bias, __nv_bfloat16* __restrict__ outb)
{
    extern __shared__ float smf[];
    float* As = smf;                        // 128 x A5_STRIDE
    float* Bs = smf + 128 * A5_STRIDE;      // 2 stages of 32 x B5_STRIDE

    int tid  = threadIdx.x;
    int lane = tid & 31;
    int wid  = tid >> 5;
    int wr   = wid >> 1;
    int wc   = wid & 1;
    int g    = lane >> 2;
    int tg   = lane & 3;
    size_t m0 = (size_t)blockIdx.x * 128;

    uint32_t bs_u = smem_u32(Bs);

    // load full A panel (128 x 128 bf16) -> fp32 SMEM
#pragma unroll
    for (int t = 0; t < 8; t++) {
        int idx = tid + t * 256;                 // 2048 uint4 total
        int r = idx >> 4, cc = (idx & 15) * 8;
        uint4 u = *reinterpret_cast<const uint4*>(Ab + (m0 + r) * C_DIM + cc);
        __nv_bfloat162* p = reinterpret_cast<__nv_bfloat162*>(&u);
        float2 f0 = __bfloat1622float2(p[0]);
        float2 f1 = __bfloat1622float2(p[1]);
        float2 f2 = __bfloat1622float2(p[2]);
        float2 f3 = __bfloat1622float2(p[3]);
        float* d = &As[r * A5_STRIDE + cc];
        *reinterpret_cast<float4*>(d)     = make_float4(f0.x, f0.y, f1.x, f1.y);
        *reinterpret_cast<float4*>(d + 4) = make_float4(f2.x, f2.y, f3.x, f3.y);
    }

    auto loadB = [&](int nc, int kc, int s) {
#pragma unroll
        for (int t = 0; t < 4; t++) {
            int idx = tid + t * 256;
            int r = idx >> 5, cc = (idx & 31) * 4;
            cp_async16(bs_u + (uint32_t)(s * B5_SZ + r * B5_STRIDE + cc) * 4,
                       W + (size_t)(kc * 32 + r) * NTOT + nc * 128 + cc);
        }
        asm volatile("cp.async.commit_group;" ::: "memory");
    };

    constexpr int NCH = NTOT / 128;
#pragma unroll 1
    for (int nc = 0; nc < NCH; nc++) {
        float c[2][8][4];
#pragma unroll
        for (int i = 0; i < 2; i++)
#pragma unroll
            for (int j = 0; j < 8; j++)
#pragma unroll
                for (int q = 0; q < 4; q++) c[i][j][q] = 0.0f;

        loadB(nc, 0, 0);
#pragma unroll
        for (int kc = 0; kc < 4; kc++) {
            int s = kc & 1;
            if (kc < 3) {
                loadB(nc, kc + 1, s ^ 1);
                asm volatile("cp.async.wait_group 1;" ::: "memory");
            } else {
                asm volatile("cp.async.wait_group 0;" ::: "memory");
            }
            __syncthreads();
            const float* Bp = Bs + s * B5_SZ;
#pragma unroll
            for (int kb = 0; kb < 4; kb++) {
                int col = kc * 32 + kb * 8 + tg;
                uint32_t a[2][4], b[8][2];
#pragma unroll
                for (int i = 0; i < 2; i++) {
                    int row = wr * 32 + i * 16 + g;
                    a[i][0] = __float_as_uint(As[row * A5_STRIDE + col]);
                    a[i][1] = __float_as_uint(As[(row + 8) * A5_STRIDE + col]);
                    a[i][2] = __float_as_uint(As[row * A5_STRIDE + col + 4]);
                    a[i][3] = __float_as_uint(As[(row + 8) * A5_STRIDE + col + 4]);
                }
#pragma unroll
                for (int j = 0; j < 8; j++) {
                    int n = wc * 64 + j * 8 + g;
                    b[j][0] = __float_as_uint(Bp[(kb * 8 + tg) * B5_STRIDE + n]);
                    b[j][1] = __float_as_uint(Bp[(kb * 8 + tg + 4) * B5_STRIDE + n]);
                }
#pragma unroll
                for (int i = 0; i < 2; i++)
#pragma unroll
                    for (int j = 0; j < 8; j++)
                        mma_tf32(c[i][j], a[i], b[j]);
            }
            __syncthreads();
        }

        // epilogue for this n-chunk
#pragma unroll
        for (int i = 0; i < 2; i++) {
#pragma unroll
            for (int half = 0; half < 2; half++) {
                size_t grow = m0 + wr * 32 + i * 16 + g + half * 8;
#pragma unroll
                for (int j = 0; j < 8; j++) {
                    int colg = nc * 128 + wc * 64 + j * 8 + tg * 2;
                    float v0 = c[i][j][half * 2]     + __ldg(&bias[colg]);
                    float v1 = c[i][j][half * 2 + 1] + __ldg(&bias[colg + 1]);
                    if constexpr (EPI == 2) {
                        v0 = 0.5f * v0 * (1.0f + erff(v0 * 0.7071067811865476f));
                        v1 = 0.5f * v1 * (1.0f + erff(v1 * 0.7071067811865476f));
                    }
                    *reinterpret_cast<__nv_bfloat162*>(outb + grow * NTOT + colg) =
                        __floats2bfloat162_rn(v0, v1);
                }
            }
        }
    }
}

// ---------------------------------------------------------------------------
// GEMM4 (streaming): tf32 warp-MMA, 128x128 block, bf16 A, K-streamed.
//   EPI 1: +bias, scatter via g_m*   EPI 3: +bias, g_y + evec*acc -> out[g_asyrow]
// ---------------------------------------------------------------------------
#define AS_STRIDE 36
#define BS_STRIDE 136
#define GEMM_ASZ (128 * AS_STRIDE)
#define GEMM_BSZ (32 * BS_STRIDE)
#define GEMM_SMEM_BYTES ((2 * GEMM_ASZ + 2 * GEMM_BSZ) * 4)

template<int NTOT, int KTOT, int EPI>
__global__ void __launch_bounds__(256) gemm4_kernel(
    const __nv_bfloat16* __restrict__ Ab, const float* __restrict__ W,
    const float* __restrict__ bias, float* __restrict__ outv,
    const float* __restrict__ evec)
{
    extern __shared__ float smf[];
    float* As = smf;
    float* Bs = smf + 2 * GEMM_ASZ;

    int tid  = threadIdx.x;
    int lane = tid & 31;
    int wid  = tid >> 5;
    int wr   = wid >> 1;
    int wc   = wid & 1;
    int g    = lane >> 2;
    int tg   = lane & 3;
    size_t m0 = (size_t)blockIdx.x * 128;
    constexpr int NC = KTOT / 32;

    uint32_t bs_u = smem_u32(Bs);

    uint4 areg[2];
    auto ldgA = [&](int kc) {
#pragma unroll
        for (int t = 0; t < 2; t++) {
            int idx = tid + t * 256;
            int r = idx >> 2, cc = (idx & 3) * 8;
            areg[t] = *reinterpret_cast<const uint4*>(
                Ab + (m0 + r) * KTOT + kc * 32 + cc);
        }
    };
    auto stsA = [&](int s) {
#pragma unroll
        for (int t = 0; t < 2; t++) {
            int idx = tid + t * 256;
            int r = idx >> 2, cc = (idx & 3) * 8;
            __nv_bfloat162* p = reinterpret_cast<__nv_bfloat162*>(&areg[t]);
            float2 f0 = __bfloat1622float2(p[0]);
            float2 f1 = __bfloat1622float2(p[1]);
            float2 f2 = __bfloat1622float2(p[2]);
            float2 f3 = __bfloat1622float2(p[3]);
            float* d = &As[s * GEMM_ASZ + r * AS_STRIDE + cc];
            *reinterpret_cast<float4*>(d)     = make_float4(f0.x, f0.y, f1.x, f1.y);
            *reinterpret_cast<float4*>(d + 4) = make_float4(f2.x, f2.y, f3.x, f3.y);
        }
    };
    auto loadB = [&](int kc, int s) {
#pragma unroll
        for (int t = 0; t < 4; t++) {
            int idx = tid + t * 256;
            int r = idx >> 5, cc = (idx & 31) * 4;
            cp_async16(bs_u + (uint32_t)(s * GEMM_BSZ + r * BS_STRIDE + cc) * 4,
                       W + (size_t)(kc * 32 + r) * NTOT + cc);
        }
        asm volatile("cp.async.commit_group;" ::: "memory");
    };

    float c[2][8][4];
#pragma unroll
    for (int i = 0; i < 2; i++)
#pragma unroll
        for (int j = 0; j < 8; j++)
#pragma unroll
            for (int q = 0; q < 4; q++) c[i][j][q] = 0.0f;

    ldgA(0);
    loadB(0, 0);
    stsA(0);
    for (int kc = 0; kc < NC; kc++) {
        int s = kc & 1;
        if (kc + 1 < NC) {
            loadB(kc + 1, s ^ 1);
            asm volatile("cp.async.wait_group 1;" ::: "memory");
        } else {
            asm volatile("cp.async.wait_group 0;" ::: "memory");
        }
        __syncthreads();
        if (kc + 1 < NC) ldgA(kc + 1);

        const float* Ap = As + s * GEMM_ASZ;
        const float* Bp = Bs + s * GEMM_BSZ;
#pragma unroll
        for (int kb = 0; kb < 4; kb++) {
            uint32_t a[2][4], b[8][2];
#pragma unroll
            for (int i = 0; i < 2; i++) {
                int row = wr * 32 + i * 16 + g;
                a[i][0] = __float_as_uint(Ap[row * AS_STRIDE + kb * 8 + tg]);
                a[i][1] = __float_as_uint(Ap[(row + 8) * AS_STRIDE + kb * 8 + tg]);
                a[i][2] = __float_as_uint(Ap[row * AS_STRIDE + kb * 8 + tg + 4]);
                a[i][3] = __float_as_uint(Ap[(row + 8) * AS_STRIDE + kb * 8 + tg + 4]);
            }
#pragma unroll
            for (int j = 0; j < 8; j++) {
                int n = wc * 64 + j * 8 + g;
                b[j][0] = __float_as_uint(Bp[(kb * 8 + tg) * BS_STRIDE + n]);
                b[j][1] = __float_as_uint(Bp[(kb * 8 + tg + 4) * BS_STRIDE + n]);
            }
#pragma unroll
            for (int i = 0; i < 2; i++)
#pragma unroll
                for (int j = 0; j < 8; j++)
                    mma_tf32(c[i][j], a[i], b[j]);
        }
        __syncthreads();
        if (kc + 1 < NC) stsA(s ^ 1);
    }

#pragma unroll
    for (int i = 0; i < 2; i++) {
#pragma unroll
        for (int half = 0; half < 2; half++) {
            size_t grow = m0 + wr * 32 + i * 16 + g + half * 8;
            float* dstf;
            int f = 0;
            if constexpr (EPI == 1) {
                f = g_mflag[grow];
                dstf = (f == 1) ? (g_att + (size_t)g_mrank[grow] * C_DIM)
                                : (outv + (size_t)g_mrow[grow] * C_DIM);
            } else {
                dstf = outv + (size_t)g_asyrow[grow] * C_DIM;
            }
#pragma unroll
            for (int j = 0; j < 8; j++) {
                int colg = wc * 64 + j * 8 + tg * 2;
                float v0 = c[i][j][half * 2]     + __ldg(&bias[colg]);
                float v1 = c[i][j][half * 2 + 1] + __ldg(&bias[colg + 1]);
                if constexpr (EPI == 3) {
                    v0 = g_y[grow * C_DIM + colg]     + __ldg(&evec[colg]) * v0;
                    v1 = g_y[grow * C_DIM + colg + 1] + __ldg(&evec[colg + 1]) * v1;
                }
                if constexpr (EPI == 1) {
                    if (f != 2)
                        *reinterpret_cast<float2*>(dstf + colg) = make_float2(v0, v1);
                } else {
                    *reinterpret_cast<float2*>(dstf + colg) = make_float2(v0, v1);
                }
            }
        }
    }
}

// ---------------------------------------------------------------------------
// attention per partition. g_qkv_bf (64x384) -> g_o_bf (64x128).
// ---------------------------------------------------------------------------
#define QS3 388
#define SS3 66
#define ATTN3_SMEM_BYTES ((64 * QS3 + 4 * 64 * SS3) * 4 + 256)

__global__ void __launch_bounds__(256, 1) attn3_kernel(
    const __nv_bfloat16* __restrict__ gqkv, __nv_bfloat16* __restrict__ go)
{
    extern __shared__ float sm[];
    float* qsm = sm;
    float* ssm = sm + 64 * QS3;
    int* kfl   = (int*)(ssm + 4 * 64 * SS3);

    int m   = blockIdx.x;
    int tid = threadIdx.x;
    if (tid < 64) kfl[tid] = g_mflag[m * 64 + tid];

    const uint4* src = reinterpret_cast<const uint4*>(gqkv + (size_t)m * 64 * 384);
    for (int i = tid; i < 3072; i += 256) {
        int r = i / 48, c8 = (i - r * 48) * 8;
        uint4 u = src[i];
        float2 f0 = __bfloat1622float2(*reinterpret_cast<__nv_bfloat162*>(&u.x));
        float2 f1 = __bfloat1622float2(*reinterpret_cast<__nv_bfloat162*>(&u.y));
        float2 f2 = __bfloat1622float2(*reinterpret_cast<__nv_bfloat162*>(&u.z));
        float2 f3 = __bfloat1622float2(*reinterpret_cast<__nv_bfloat162*>(&u.w));
        float* d = &qsm[r * QS3 + c8];
        d[0] = f0.x; d[1] = f0.y; d[2] = f1.x; d[3] = f1.y;
        d[4] = f2.x; d[5] = f2.y; d[6] = f3.x; d[7] = f3.y;
    }
    __syncthreads();

    int wid = tid >> 5, lane = tid & 31;
    int g = lane >> 2, tg = lane & 3;
    int h = wid >> 1;
    int rbase = (wid & 1) * 32;
    int bq = h * 96, bk = bq + 32, bv = bq + 64;
    float* ssh = ssm + h * 64 * SS3;
    const float scale = 0.17677669529663687f;

    float c[2][8][4];
#pragma unroll
    for (int i = 0; i < 2; i++)
#pragma unroll
        for (int j = 0; j < 8; j++)
#pragma unroll
            for (int q = 0; q < 4; q++) c[i][j][q] = 0.0f;

#pragma unroll
    for (int kt = 0; kt < 4; kt++) {
        uint32_t a[2][4], b[8][2];
#pragma unroll
        for (int i = 0; i < 2; i++) {
            int row = rbase + i * 16 + g;
            a[i][0] = __float_as_uint(qsm[row * QS3 + bq + kt * 8 + tg]);
            a[i][1] = __float_as_uint(qsm[(row + 8) * QS3 + bq + kt * 8 + tg]);
            a[i][2] = __float_as_uint(qsm[row * QS3 + bq + kt * 8 + tg + 4]);
            a[i][3] = __float_as_uint(qsm[(row + 8) * QS3 + bq + kt * 8 + tg + 4]);
        }
#pragma unroll
        for (int j = 0; j < 8; j++) {
            int n = j * 8 + g;
            b[j][0] = __float_as_uint(qsm[n * QS3 + bk + kt * 8 + tg]);
            b[j][1] = __float_as_uint(qsm[n * QS3 + bk + kt * 8 + tg + 4]);
        }
#pragma unroll
        for (int i = 0; i < 2; i++)
#pragma unroll
            for (int j = 0; j < 8; j++)
                mma_tf32(c[i][j], a[i], b[j]);
    }

    unsigned mask = 0;
#pragma unroll
    for (int j = 0; j < 8; j++)
#pragma unroll
        for (int q = 0; q < 2; q++)
            if (kfl[j * 8 + 2 * tg + q] == 2) mask |= 1u << (j * 2 + q);

#pragma unroll
    for (int i = 0; i < 2; i++) {
#pragma unroll
        for (int sel = 0; sel < 2; sel++) {
            float mx = -1e30f;
#pragma unroll
            for (int j = 0; j < 8; j++)
#pragma unroll
                for (int q = 0; q < 2; q++) {
                    float v = c[i][j][sel * 2 + q] * scale;
                    if (mask & (1u << (j * 2 + q))) v = -10000.0f;
                    c[i][j][sel * 2 + q] = v;
                    mx = fmaxf(mx, v);
                }
            mx = fmaxf(mx, __shfl_xor_sync(0xffffffffu, mx, 1));
            mx = fmaxf(mx, __shfl_xor_sync(0xffffffffu, mx, 2));
            float s = 0.0f;
#pragma unroll
            for (int j = 0; j < 8; j++)
#pragma unroll
                for (int q = 0; q < 2; q++) {
                    float e = __expf(c[i][j][sel * 2 + q] - mx);
                    c[i][j][sel * 2 + q] = e;
                    s += e;
                }
            s += __shfl_xor_sync(0xffffffffu, s, 1);
            s += __shfl_xor_sync(0xffffffffu, s, 2);
            float rinv = 1.0f / s;
            int row = rbase + i * 16 + g + sel * 8;
#pragma unroll
            for (int j = 0; j < 8; j++)
#pragma unroll
                for (int q = 0; q < 2; q++)
                    ssh[row * SS3 + j * 8 + 2 * tg + q] = c[i][j][sel * 2 + q] * rinv;
        }
    }
    __syncwarp();

    float o[2][4][4];
#pragma unroll
    for (int i = 0; i < 2; i++)
#pragma unroll
        for (int j = 0; j < 4; j++)
#pragma unroll
            for (int q = 0; q < 4; q++) o[i][j][q] = 0.0f;

#pragma unroll
    for (int kt = 0; kt < 8; kt++) {
        uint32_t a[2][4], b[4][2];
#pragma unroll
        for (int i = 0; i < 2; i++) {
            int row = rbase + i * 16 + g;
            a[i][0] = __float_as_uint(ssh[row * SS3 + kt * 8 + tg]);
            a[i][1] = __float_as_uint(ssh[(row + 8) * SS3 + kt * 8 + tg]);
            a[i][2] = __float_as_uint(ssh[row * SS3 + kt * 8 + tg + 4]);
            a[i][3] = __float_as_uint(ssh[(row + 8) * SS3 + kt * 8 + tg + 4]);
        }
#pragma unroll
        for (int j = 0; j < 4; j++) {
            int n = j * 8 + g;
            b[j][0] = __float_as_uint(qsm[(kt * 8 + tg) * QS3 + bv + n]);
            b[j][1] = __float_as_uint(qsm[(kt * 8 + tg + 4) * QS3 + bv + n]);
        }
#pragma unroll
        for (int i = 0; i < 2; i++)
#pragma unroll
            for (int j = 0; j < 4; j++)
                mma_tf32(o[i][j], a[i], b[j]);
    }

#pragma unroll
    for (int i = 0; i < 2; i++)
#pragma unroll
        for (int j = 0; j < 4; j++) {
            size_t row = (size_t)(m * 64 + rbase + i * 16 + g);
            int col = h * 32 + j * 8 + 2 * tg;
            *reinterpret_cast<__nv_bfloat162*>(&go[row * C_DIM + col]) =
                __floats2bfloat162_rn(o[i][j][0], o[i][j][1]);
            *reinterpret_cast<__nv_bfloat162*>(&go[(row + 8) * C_DIM + col]) =
                __floats2bfloat162_rn(o[i][j][2], o[i][j][3]);
        }
}

// ---------------------------------------------------------------------------
// ybuild: y = xa + g1*att -> g_y (fp32) ; LN2(y) -> g_yn_bf (bf16)
// ---------------------------------------------------------------------------
__global__ void __launch_bounds__(256) ybuild_kernel(
    const float* __restrict__ g1,
    const float* __restrict__ ln2w, const float* __restrict__ ln2b)
{
    int r    = (int)((blockIdx.x * 256u + threadIdx.x) >> 5);
    int lane = threadIdx.x & 31;
    if (r >= A_CNT) return;
    float4 a = reinterpret_cast<const float4*>(g_xa + (size_t)r * C_DIM)[lane];
    float4 t = reinterpret_cast<const float4*>(g_att + (size_t)r * C_DIM)[lane];
    float4 gv = reinterpret_cast<const float4*>(g1)[lane];
    float4 y;
    y.x = a.x + gv.x * t.x; y.y = a.y + gv.y * t.y;
    y.z = a.z + gv.z * t.z; y.w = a.w + gv.w * t.w;
    reinterpret_cast<float4*>(g_y + (size_t)r * C_DIM)[lane] = y;
    float s1 = y.x + y.y + y.z + y.w;
    float s2 = y.x*y.x + y.y*y.y + y.z*y.z + y.w*y.w;
    warp_sum2(s1, s2);
    float m = s1 * (1.0f / C_DIM);
    float var = s2 * (1.0f / C_DIM) - m * m;
    float inv = rsqrtf(var + EPS_LN);
    float4 wv = reinterpret_cast<const float4*>(ln2w)[lane];
    float4 bv = reinterpret_cast<const float4*>(ln2b)[lane];
    __nv_bfloat162 b0 = __floats2bfloat162_rn(
        (y.x - m) * inv * wv.x + bv.x, (y.y - m) * inv * wv.y + bv.y);
    __nv_bfloat162 b1 = __floats2bfloat162_rn(
        (y.z - m) * inv * wv.z + bv.z, (y.w - m) * inv * wv.w + bv.w);
    uint2 u;
    u.x = *reinterpret_cast<uint32_t*>(&b0);
    u.y = *reinterpret_cast<uint32_t*>(&b1);
    *reinterpret_cast<uint2*>(g_yn_bf + (size_t)r * C_DIM + lane * 4) = u;
}

// ---------------------------------------------------------------------------
extern "C" void kernel_launch(void* const* d_in, const int* in_sizes, int n_in,
                              void* d_out, int out_size)
{
    int base = 7;
    if (n_in == 19) base = 5;

    const float* x      = (const float*)d_in[0];
    const int*   iw     = (const int*)d_in[1];
    const int*   ipart  = (const int*)d_in[2];
    const int*   asy    = (const int*)d_in[3];
    const int*   blk    = (const int*)d_in[4];
    const float* ln1w   = (const float*)d_in[base + 0];
    const float* ln1b   = (const float*)d_in[base + 1];
    const float* qkvw   = (const float*)d_in[base + 2];
    const float* qkvb   = (const float*)d_in[base + 3];
    const float* projw  = (const float*)d_in[base + 4];
    const float* projb  = (const float*)d_in[base + 5];
    const float* g1     = (const float*)d_in[base + 6];
    const float* ln2w   = (const float*)d_in[base + 7];
    const float* ln2b   = (const float*)d_in[base + 8];
    const float* w1     = (const float*)d_in[base + 9];
    const float* b1     = (const float*)d_in[base + 10];
    const float* w2     = (const float*)d_in[base + 11];
    const float* b2     = (const float*)d_in[base + 12];
    const float* g2     = (const float*)d_in[base + 13];
    float* out = (float*)d_out;

    __nv_bfloat16 *p_xp, *p_qkv, *p_o, *p_yn, *p_h;
    cudaGetSymbolAddress((void**)&p_xp, g_xp_bf);
    cudaGetSymbolAddress((void**)&p_qkv, g_qkv_bf);
    cudaGetSymbolAddress((void**)&p_o, g_o_bf);
    cudaGetSymbolAddress((void**)&p_yn, g_yn_bf);
    cudaGetSymbolAddress((void**)&p_h, g_h_bf);

    cudaFuncSetAttribute(gemm5_kernel<384, 0>,
                         cudaFuncAttributeMaxDynamicSharedMemorySize, GEMM5_SMEM_BYTES);
    cudaFuncSetAttribute(gemm5_kernel<512, 2>,
                         cudaFuncAttributeMaxDynamicSharedMemorySize, GEMM5_SMEM_BYTES);
    cudaFuncSetAttribute(gemm4_kernel<128, 128, 1>,
                         cudaFuncAttributeMaxDynamicSharedMemorySize, GEMM_SMEM_BYTES);
    cudaFuncSetAttribute(gemm4_kernel<128, 512, 3>,
                         cudaFuncAttributeMaxDynamicSharedMemorySize, GEMM_SMEM_BYTES);
    cudaFuncSetAttribute(attn3_kernel,
                         cudaFuncAttributeMaxDynamicSharedMemorySize, ATTN3_SMEM_BYTES);

    // 0-2. init + maps + meta
    zero_misc_kernel<<<(MW_CNT / 16 + N_WIN / 4 + 255) / 256, 256>>>();
    set_maps_kernel<<<MW_CNT / 256, 256>>>(asy, blk, iw, ipart);
    meta_kernel<<<MW_CNT / 256, 256>>>(ipart, iw);
    // 3. fused LN + double-LN + scatter to xp
    ln_kernel<<<N_TOK / 16, 256>>>(x, ln1w, ln1b, out);
    // 4. QKV GEMM (A-resident) -> bf16
    gemm5_kernel<384, 0><<<MW_CNT / 128, 256, GEMM5_SMEM_BYTES>>>(
        p_xp, qkvw, qkvb, p_qkv);
    // 5. attention (tensor cores) -> bf16
    attn3_kernel<<<M_PART, 256, ATTN3_SMEM_BYTES>>>(p_qkv, p_o);
    // 6. proj GEMM + scatter (fp32 out)
    gemm4_kernel<128, 128, 1><<<MW_CNT / 128, 256, GEMM_SMEM_BYTES>>>(
        p_o, projw, projb, out, nullptr);
    // 7. y build + LN2 (bf16 yn)
    ybuild_kernel<<<A_CNT / 8, 256>>>(g1, ln2w, ln2b);
    // 8. MLP GEMM1 (A-resident) + gelu -> bf16
    gemm5_kernel<512, 2><<<A_CNT / 128, 256, GEMM5_SMEM_BYTES>>>(
        p_yn, w1, b1, p_h);
    // 9. MLP GEMM2 + residual + scatter (fp32 out)
    gemm4_kernel<128, 512, 3><<<A_CNT / 128, 256, GEMM_SMEM_BYTES>>>(
        p_h, w2, b2, out, g2);
}

// round 9
// speedup vs baseline: 1.2179x; 1.1244x over previous
#include <cuda_runtime.h>
#include <cuda_bf16.h>
#include <math.h>
#include <stdint.h>

// Problem constants
#define N_TOK   524288
#define N_WIN   8192
#define P_TOK   64
#define C_DIM   128
#define M_PART  4096
#define MW_CNT  262144
#define A_CNT   131072
#define BL_CNT  65536
#define EPS_LN  1e-6f

// ---------------------------------------------------------------------------
// Scratch (device globals — allocation-free rule)
// ---------------------------------------------------------------------------
__device__ float g_xa[(size_t)A_CNT * C_DIM];
__device__ float g_att[(size_t)A_CNT * C_DIM];
__device__ float g_y[(size_t)A_CNT * C_DIM];
__device__ __nv_bfloat16 g_xp_bf[(size_t)MW_CNT * C_DIM];
__device__ __nv_bfloat16 g_qkv_bf[(size_t)MW_CNT * 384];
__device__ __nv_bfloat16 g_o_bf[(size_t)MW_CNT * C_DIM];
__device__ __nv_bfloat16 g_yn_bf[(size_t)A_CNT * C_DIM];
__device__ __nv_bfloat16 g_h_bf[(size_t)A_CNT * 512];
__device__ __nv_bfloat16 g_wqkvT[384 * 128];   // WT[n][k] bf16
__device__ __nv_bfloat16 g_wprojT[128 * 128];
__device__ __nv_bfloat16 g_w1T[512 * 128];
__device__ __nv_bfloat16 g_w2T[128 * 512];
__device__ unsigned char g_flag[MW_CNT];
__device__ int g_rank[MW_CNT];
__device__ int g_ipos[MW_CNT];
__device__ int g_winv[N_WIN];
__device__ int g_asyrow[A_CNT];
__device__ unsigned char g_mflag[MW_CNT];
__device__ int g_mrow[MW_CNT];
__device__ int g_mrank[MW_CNT];

// ---------------------------------------------------------------------------
// helpers
// ---------------------------------------------------------------------------
__device__ __forceinline__ void mma_tf32(float c[4], const uint32_t a[4], const uint32_t b[2]) {
    asm volatile(
        "mma.sync.aligned.m16n8k8.row.col.f32.tf32.tf32.f32 "
        "{%0,%1,%2,%3}, {%4,%5,%6,%7}, {%8,%9}, {%0,%1,%2,%3};"
        : "+f"(c[0]), "+f"(c[1]), "+f"(c[2]), "+f"(c[3])
        : "r"(a[0]), "r"(a[1]), "r"(a[2]), "r"(a[3]), "r"(b[0]), "r"(b[1]));
}
__device__ __forceinline__ void mma_bf16(float c[4], const uint32_t a[4], const uint32_t b[2]) {
    asm volatile(
        "mma.sync.aligned.m16n8k16.row.col.f32.bf16.bf16.f32 "
        "{%0,%1,%2,%3}, {%4,%5,%6,%7}, {%8,%9}, {%0,%1,%2,%3};"
        : "+f"(c[0]), "+f"(c[1]), "+f"(c[2]), "+f"(c[3])
        : "r"(a[0]), "r"(a[1]), "r"(a[2]), "r"(a[3]), "r"(b[0]), "r"(b[1]));
}
__device__ __forceinline__ uint32_t smem_u32(const void* p) {
    uint32_t a;
    asm("{ .reg .u64 t; cvta.to.shared.u64 t, %1; cvt.u32.u64 %0, t; }" : "=r"(a) : "l"(p));
    return a;
}
__device__ __forceinline__ void cp_async16(uint32_t dst, const void* src) {
    asm volatile("cp.async.cg.shared.global [%0], [%1], 16;" :: "r"(dst), "l"(src) : "memory");
}
__device__ __forceinline__ void warp_sum2(float& s1, float& s2) {
#pragma unroll
    for (int o = 16; o; o >>= 1) {
        s1 += __shfl_xor_sync(0xffffffffu, s1, o);
        s2 += __shfl_xor_sync(0xffffffffu, s2, o);
    }
}
__device__ __forceinline__ void warp_sum4(float& a1, float& a2, float& b1, float& b2) {
#pragma unroll
    for (int o = 16; o; o >>= 1) {
        a1 += __shfl_xor_sync(0xffffffffu, a1, o);
        a2 += __shfl_xor_sync(0xffffffffu, a2, o);
        b1 += __shfl_xor_sync(0xffffffffu, b1, o);
        b2 += __shfl_xor_sync(0xffffffffu, b2, o);
    }
}

// ---------------------------------------------------------------------------
// K0: init
// ---------------------------------------------------------------------------
__global__ void __launch_bounds__(256) zero_misc_kernel()
{
    int t = blockIdx.x * 256 + threadIdx.x;
    if (t < MW_CNT / 16)
        reinterpret_cast<uint4*>(g_flag)[t] = make_uint4(0u, 0u, 0u, 0u);
    int u = t - MW_CNT / 16;
    if (u >= 0 && u < N_WIN / 4)
        reinterpret_cast<int4*>(g_winv)[u] = make_int4(-1, -1, -1, -1);
}

// ---------------------------------------------------------------------------
// K1: index maps
// ---------------------------------------------------------------------------
__global__ void __launch_bounds__(256) set_maps_kernel(
    const int* __restrict__ asy, const int* __restrict__ blk,
    const int* __restrict__ iw, const int* __restrict__ ipart)
{
    int t = blockIdx.x * 256 + threadIdx.x;
    if (t < MW_CNT) g_ipos[ipart[t]] = t;
    if (t < A_CNT) {
        int g = asy[t];
        g_flag[g] = 1;
        g_rank[g] = t;
        g_asyrow[t] = iw[g >> 6] * 64 + (g & 63);
    } else if (t < A_CNT + BL_CNT) {
        g_flag[blk[t - A_CNT]] = 2;
    }
    if (t < M_PART) g_winv[iw[t]] = t;
}

// ---------------------------------------------------------------------------
// K2: partition-order meta
// ---------------------------------------------------------------------------
__global__ void __launch_bounds__(256) meta_kernel(
    const int* __restrict__ ipart, const int* __restrict__ iw)
{
    int i = blockIdx.x * 256 + threadIdx.x;
    if (i >= MW_CNT) return;
    int g = ipart[i];
    int f = g_flag[g];
    g_mflag[i] = (unsigned char)f;
    g_mrow[i]  = iw[g >> 6] * 64 + (g & 63);
    g_mrank[i] = (f == 1) ? g_rank[g] : 0;
}

// ---------------------------------------------------------------------------
// K2b: weight transpose+quantize  W[K,N] fp32 -> WT[N,K] bf16
// ---------------------------------------------------------------------------
__global__ void __launch_bounds__(256) wtrans_kernel(
    const float* __restrict__ W, __nv_bfloat16* __restrict__ WT, int K, int N)
{
    int idx = blockIdx.x * 256 + threadIdx.x;
    if (idx >= K * N) return;
    int k = idx / N, n = idx - k * N;
    WT[n * K + k] = __float2bfloat16(W[idx]);
}

// ---------------------------------------------------------------------------
// K3: fused LN + scatter (unchanged from R8)
// ---------------------------------------------------------------------------
__global__ void __launch_bounds__(256) ln_kernel(
    const float* __restrict__ x, const float* __restrict__ w,
    const float* __restrict__ b, float* __restrict__ out)
{
    int wglob = blockIdx.x * 8 + (threadIdx.x >> 5);
    int lane  = threadIdx.x & 31;
    int r0 = wglob * 2;
    int r1 = r0 + 1;

    float4 v0 = reinterpret_cast<const float4*>(x + (size_t)r0 * C_DIM)[lane];
    float4 v1 = reinterpret_cast<const float4*>(x + (size_t)r1 * C_DIM)[lane];
    float4 wv = reinterpret_cast<const float4*>(w)[lane];
    float4 bv = reinterpret_cast<const float4*>(b)[lane];

    float a1 = v0.x + v0.y + v0.z + v0.w;
    float a2 = v0.x*v0.x + v0.y*v0.y + v0.z*v0.z + v0.w*v0.w;
    float c1 = v1.x + v1.y + v1.z + v1.w;
    float c2 = v1.x*v1.x + v1.y*v1.y + v1.z*v1.z + v1.w*v1.w;
    warp_sum4(a1, a2, c1, c2);

#pragma unroll
    for (int rr = 0; rr < 2; rr++) {
        int row = rr ? r1 : r0;
        float4 v = rr ? v1 : v0;
        float s1 = rr ? c1 : a1;
        float s2 = rr ? c2 : a2;
        float m = s1 * (1.0f / C_DIM);
        float var = s2 * (1.0f / C_DIM) - m * m;
        float inv = rsqrtf(var + EPS_LN);
        float4 r;
        r.x = (v.x - m) * inv * wv.x + bv.x; r.y = (v.y - m) * inv * wv.y + bv.y;
        r.z = (v.z - m) * inv * wv.z + bv.z; r.w = (v.w - m) * inv * wv.w + bv.w;

        int n = row >> 6, p = row & 63;
        int widx = g_winv[n];
        if (widx < 0) {
            reinterpret_cast<float4*>(out + (size_t)row * C_DIM)[lane] = r;
        } else {
            int g = widx * 64 + p;
            int f = g_flag[g];
            int ipos = g_ipos[g];
            float4 val = r;
            if (f == 2) {
                reinterpret_cast<float4*>(out + (size_t)row * C_DIM)[lane] = r;
            } else if (f == 1) {
                float t1 = r.x + r.y + r.z + r.w;
                float t2 = r.x*r.x + r.y*r.y + r.z*r.z + r.w*r.w;
                warp_sum2(t1, t2);
                float m2 = t1 * (1.0f / C_DIM);
                float var2 = t2 * (1.0f / C_DIM) - m2 * m2;
                float inv2 = rsqrtf(var2 + EPS_LN);
                val.x = (r.x - m2) * inv2 * wv.x + bv.x;
                val.y = (r.y - m2) * inv2 * wv.y + bv.y;
                val.z = (r.z - m2) * inv2 * wv.z + bv.z;
                val.w = (r.w - m2) * inv2 * wv.w + bv.w;
                reinterpret_cast<float4*>(g_xa + (size_t)g_rank[g] * C_DIM)[lane] = val;
            }
            __nv_bfloat162 b0 = __floats2bfloat162_rn(val.x, val.y);
            __nv_bfloat162 b1 = __floats2bfloat162_rn(val.z, val.w);
            uint2 u;
            u.x = *reinterpret_cast<uint32_t*>(&b0);
            u.y = *reinterpret_cast<uint32_t*>(&b1);
            *reinterpret_cast<uint2*>(g_xp_bf + (size_t)ipos * C_DIM + lane * 4) = u;
        }
    }
}

// ---------------------------------------------------------------------------
// GEMM5B: bf16 m16n8k16 warp-MMA, A-resident (full 128x128 bf16 panel in
// SMEM), n-chunk loop with cp.async double-buffered bf16 B (WT[n][k]).
//   8 warps 4x2, warp tile 32x64.   EPI 0: +bias   EPI 2: +bias+gelu
// ---------------------------------------------------------------------------
#define SA5W 68            // A row stride in words (136 bf16, 272 B)
#define SB5W 20            // B row stride in words (40 bf16, 80 B)
#define B5WORDS (128 * SB5W)
#define GEMM5B_SMEM_BYTES ((128 * SA5W + 2 * B5WORDS) * 4)

template<int NTOT, int EPI>
__global__ void __launch_bounds__(256) gemm5b_kernel(
    const __nv_bfloat16* __restrict__ Ab, const __nv_bfloat16* __restrict__ WT,
    const float* __restrict__ bias, __nv_bfloat16* __restrict__ outb)
{
    extern __shared__ uint32_t smu[];
    uint32_t* As = smu;                     // 128 x SA5W words
    uint32_t* Bs = smu + 128 * SA5W;        // 2 stages x 128 x SB5W words

    int tid  = threadIdx.x;
    int lane = tid & 31;
    int wid  = tid >> 5;
    int wr   = wid >> 1;
    int wc   = wid & 1;
    int g    = lane >> 2;
    int tg   = lane & 3;
    size_t m0 = (size_t)blockIdx.x * 128;

    uint32_t as_u = smem_u32(As);
    uint32_t bs_u = smem_u32(Bs);

    // A panel: 128 rows x 256B = 2048 16B txns (8 per thread)
#pragma unroll
    for (int t = 0; t < 8; t++) {
        int idx = tid + t * 256;
        int r = idx >> 4, cc = idx & 15;
        cp_async16(as_u + (uint32_t)(r * (SA5W * 4) + cc * 16),
                   Ab + (m0 + r) * C_DIM + cc * 8);
    }

    auto loadB = [&](int nc, int kc, int s) {
#pragma unroll
        for (int t = 0; t < 2; t++) {
            int idx = tid + t * 256;
            int r = idx >> 2, cc = idx & 3;
            cp_async16(bs_u + (uint32_t)(s * (B5WORDS * 4) + r * (SB5W * 4) + cc * 16),
                       WT + (size_t)(nc * 128 + r) * C_DIM + kc * 32 + cc * 8);
        }
        asm volatile("cp.async.commit_group;" ::: "memory");
    };

    loadB(0, 0, 0);   // A txns + B(0,0) in one group

    constexpr int NCH = NTOT / 128;
#pragma unroll 1
    for (int nc = 0; nc < NCH; nc++) {
        if (nc > 0) loadB(nc, 0, 0);
        float c[2][8][4];
#pragma unroll
        for (int i = 0; i < 2; i++)
#pragma unroll
            for (int j = 0; j < 8; j++)
#pragma unroll
                for (int q = 0; q < 4; q++) c[i][j][q] = 0.0f;

#pragma unroll
        for (int kc = 0; kc < 4; kc++) {
            int s = kc & 1;
            if (kc < 3) {
                loadB(nc, kc + 1, s ^ 1);
                asm volatile("cp.async.wait_group 1;" ::: "memory");
            } else {
                asm volatile("cp.async.wait_group 0;" ::: "memory");
            }
            __syncthreads();
            const uint32_t* Bp = Bs + s * B5WORDS;
#pragma unroll
            for (int kk = 0; kk < 2; kk++) {
                int kw = kc * 16 + kk * 8 + tg;       // word offset in A row
                uint32_t a[2][4], b[8][2];
#pragma unroll
                for (int i = 0; i < 2; i++) {
                    int row = wr * 32 + i * 16 + g;
                    a[i][0] = As[row * SA5W + kw];
                    a[i][1] = As[(row + 8) * SA5W + kw];
                    a[i][2] = As[row * SA5W + kw + 4];
                    a[i][3] = As[(row + 8) * SA5W + kw + 4];
                }
#pragma unroll
                for (int j = 0; j < 8; j++) {
                    int n = wc * 64 + j * 8 + g;
                    b[j][0] = Bp[n * SB5W + kk * 8 + tg];
                    b[j][1] = Bp[n * SB5W + kk * 8 + tg + 4];
                }
#pragma unroll
                for (int i = 0; i < 2; i++)
#pragma unroll
                    for (int j = 0; j < 8; j++)
                        mma_bf16(c[i][j], a[i], b[j]);
            }
            __syncthreads();
        }

        // epilogue for this n-chunk
#pragma unroll
        for (int i = 0; i < 2; i++) {
#pragma unroll
            for (int half = 0; half < 2; half++) {
                size_t grow = m0 + wr * 32 + i * 16 + g + half * 8;
#pragma unroll
                for (int j = 0; j < 8; j++) {
                    int colg = nc * 128 + wc * 64 + j * 8 + tg * 2;
                    float v0 = c[i][j][half * 2]     + __ldg(&bias[colg]);
                    float v1 = c[i][j][half * 2 + 1] + __ldg(&bias[colg + 1]);
                    if constexpr (EPI == 2) {
                        v0 = 0.5f * v0 * (1.0f + erff(v0 * 0.7071067811865476f));
                        v1 = 0.5f * v1 * (1.0f + erff(v1 * 0.7071067811865476f));
                    }
                    *reinterpret_cast<__nv_bfloat162*>(outb + grow * NTOT + colg) =
                        __floats2bfloat162_rn(v0, v1);
                }
            }
        }
    }
}

// ---------------------------------------------------------------------------
// GEMM4B: bf16 m16n8k16 warp-MMA, streaming K, cp.async double-buffered A+B.
//   NTOT = 128.  EPI 1: +bias, scatter via g_m*   EPI 3: residual+scatter
// ---------------------------------------------------------------------------
#define S4W 20             // row stride in words (40 bf16, 80 B) for A and B
#define A4WORDS (128 * S4W)
#define B4WORDS (128 * S4W)
#define GEMM4B_SMEM_BYTES ((2 * A4WORDS + 2 * B4WORDS) * 4)

template<int KTOT, int EPI>
__global__ void __launch_bounds__(256) gemm4b_kernel(
    const __nv_bfloat16* __restrict__ Ab, const __nv_bfloat16* __restrict__ WT,
    const float* __restrict__ bias, float* __restrict__ outv,
    const float* __restrict__ evec)
{
    extern __shared__ uint32_t smu[];
    uint32_t* As = smu;                     // 2 stages x 128 x S4W
    uint32_t* Bs = smu + 2 * A4WORDS;       // 2 stages x 128 x S4W

    int tid  = threadIdx.x;
    int lane = tid & 31;
    int wid  = tid >> 5;
    int wr   = wid >> 1;
    int wc   = wid & 1;
    int g    = lane >> 2;
    int tg   = lane & 3;
    size_t m0 = (size_t)blockIdx.x * 128;
    constexpr int NC = KTOT / 32;

    uint32_t as_u = smem_u32(As);
    uint32_t bs_u = smem_u32(Bs);

    auto loadAB = [&](int kc, int s) {
#pragma unroll
        for (int t = 0; t < 2; t++) {
            int idx = tid + t * 256;
            int r = idx >> 2, cc = idx & 3;
            cp_async16(as_u + (uint32_t)(s * (A4WORDS * 4) + r * (S4W * 4) + cc * 16),
                       Ab + (m0 + r) * KTOT + kc * 32 + cc * 8);
        }
#pragma unroll
        for (int t = 0; t < 2; t++) {
            int idx = tid + t * 256;
            int r = idx >> 2, cc = idx & 3;
            cp_async16(bs_u + (uint32_t)(s * (B4WORDS * 4) + r * (S4W * 4) + cc * 16),
                       WT + (size_t)r * KTOT + kc * 32 + cc * 8);
        }
        asm volatile("cp.async.commit_group;" ::: "memory");
    };

    float c[2][8][4];
#pragma unroll
    for (int i = 0; i < 2; i++)
#pragma unroll
        for (int j = 0; j < 8; j++)
#pragma unroll
            for (int q = 0; q < 4; q++) c[i][j][q] = 0.0f;

    loadAB(0, 0);
#pragma unroll 1
    for (int kc = 0; kc < NC; kc++) {
        int s = kc & 1;
        if (kc + 1 < NC) {
            loadAB(kc + 1, s ^ 1);
            asm volatile("cp.async.wait_group 1;" ::: "memory");
        } else {
            asm volatile("cp.async.wait_group 0;" ::: "memory");
        }
        __syncthreads();
        const uint32_t* Ap = As + s * A4WORDS;
        const uint32_t* Bp = Bs + s * B4WORDS;
#pragma unroll
        for (int kk = 0; kk < 2; kk++) {
            uint32_t a[2][4], b[8][2];
#pragma unroll
            for (int i = 0; i < 2; i++) {
                int row = wr * 32 + i * 16 + g;
                a[i][0] = Ap[row * S4W + kk * 8 + tg];
                a[i][1] = Ap[(row + 8) * S4W + kk * 8 + tg];
                a[i][2] = Ap[row * S4W + kk * 8 + tg + 4];
                a[i][3] = Ap[(row + 8) * S4W + kk * 8 + tg + 4];
            }
#pragma unroll
            for (int j = 0; j < 8; j++) {
                int n = wc * 64 + j * 8 + g;
                b[j][0] = Bp[n * S4W + kk * 8 + tg];
                b[j][1] = Bp[n * S4W + kk * 8 + tg + 4];
            }
#pragma unroll
            for (int i = 0; i < 2; i++)
#pragma unroll
                for (int j = 0; j < 8; j++)
                    mma_bf16(c[i][j], a[i], b[j]);
        }
        __syncthreads();
    }

#pragma unroll
    for (int i = 0; i < 2; i++) {
#pragma unroll
        for (int half = 0; half < 2; half++) {
            size_t grow = m0 + wr * 32 + i * 16 + g + half * 8;
            float* dstf;
            int f = 0;
            if constexpr (EPI == 1) {
                f = g_mflag[grow];
                dstf = (f == 1) ? (g_att + (size_t)g_mrank[grow] * C_DIM)
                                : (outv + (size_t)g_mrow[grow] * C_DIM);
            } else {
                dstf = outv + (size_t)g_asyrow[grow] * C_DIM;
            }
#pragma unroll
            for (int j = 0; j < 8; j++) {
                int colg = wc * 64 + j * 8 + tg * 2;
                float v0 = c[i][j][half * 2]     + __ldg(&bias[colg]);
                float v1 = c[i][j][half * 2 + 1] + __ldg(&bias[colg + 1]);
                if constexpr (EPI == 3) {
                    v0 = g_y[grow * C_DIM + colg]     + __ldg(&evec[colg]) * v0;
                    v1 = g_y[grow * C_DIM + colg + 1] + __ldg(&evec[colg + 1]) * v1;
                }
                if constexpr (EPI == 1) {
                    if (f != 2)
                        *reinterpret_cast<float2*>(dstf + colg) = make_float2(v0, v1);
                } else {
                    *reinterpret_cast<float2*>(dstf + colg) = make_float2(v0, v1);
                }
            }
        }
    }
}

// ---------------------------------------------------------------------------
// attention per partition (tf32, unchanged). g_qkv_bf -> g_o_bf.
// ---------------------------------------------------------------------------
#define QS3 388
#define SS3 66
#define ATTN3_SMEM_BYTES ((64 * QS3 + 4 * 64 * SS3) * 4 + 256)

__global__ void __launch_bounds__(256, 1) attn3_kernel(
    const __nv_bfloat16* __restrict__ gqkv, __nv_bfloat16* __restrict__ go)
{
    extern __shared__ float sm[];
    float* qsm = sm;
    float* ssm = sm + 64 * QS3;
    int* kfl   = (int*)(ssm + 4 * 64 * SS3);

    int m   = blockIdx.x;
    int tid = threadIdx.x;
    if (tid < 64) kfl[tid] = g_mflag[m * 64 + tid];

    const uint4* src = reinterpret_cast<const uint4*>(gqkv + (size_t)m * 64 * 384);
    for (int i = tid; i < 3072; i += 256) {
        int r = i / 48, c8 = (i - r * 48) * 8;
        uint4 u = src[i];
        float2 f0 = __bfloat1622float2(*reinterpret_cast<__nv_bfloat162*>(&u.x));
        float2 f1 = __bfloat1622float2(*reinterpret_cast<__nv_bfloat162*>(&u.y));
        float2 f2 = __bfloat1622float2(*reinterpret_cast<__nv_bfloat162*>(&u.z));
        float2 f3 = __bfloat1622float2(*reinterpret_cast<__nv_bfloat162*>(&u.w));
        float* d = &qsm[r * QS3 + c8];
        d[0] = f0.x; d[1] = f0.y; d[2] = f1.x; d[3] = f1.y;
        d[4] = f2.x; d[5] = f2.y; d[6] = f3.x; d[7] = f3.y;
    }
    __syncthreads();

    int wid = tid >> 5, lane = tid & 31;
    int g = lane >> 2, tg = lane & 3;
    int h = wid >> 1;
    int rbase = (wid & 1) * 32;
    int bq = h * 96, bk = bq + 32, bv = bq + 64;
    float* ssh = ssm + h * 64 * SS3;
    const float scale = 0.17677669529663687f;

    float c[2][8][4];
#pragma unroll
    for (int i = 0; i < 2; i++)
#pragma unroll
        for (int j = 0; j < 8; j++)
#pragma unroll
            for (int q = 0; q < 4; q++) c[i][j][q] = 0.0f;

#pragma unroll
    for (int kt = 0; kt < 4; kt++) {
        uint32_t a[2][4], b[8][2];
#pragma unroll
        for (int i = 0; i < 2; i++) {
            int row = rbase + i * 16 + g;
            a[i][0] = __float_as_uint(qsm[row * QS3 + bq + kt * 8 + tg]);
            a[i][1] = __float_as_uint(qsm[(row + 8) * QS3 + bq + kt * 8 + tg]);
            a[i][2] = __float_as_uint(qsm[row * QS3 + bq + kt * 8 + tg + 4]);
            a[i][3] = __float_as_uint(qsm[(row + 8) * QS3 + bq + kt * 8 + tg + 4]);
        }
#pragma unroll
        for (int j = 0; j < 8; j++) {
            int n = j * 8 + g;
            b[j][0] = __float_as_uint(qsm[n * QS3 + bk + kt * 8 + tg]);
            b[j][1] = __float_as_uint(qsm[n * QS3 + bk + kt * 8 + tg + 4]);
        }
#pragma unroll
        for (int i = 0; i < 2; i++)
#pragma unroll
            for (int j = 0; j < 8; j++)
                mma_tf32(c[i][j], a[i], b[j]);
    }

    unsigned mask = 0;
#pragma unroll
    for (int j = 0; j < 8; j++)
#pragma unroll
        for (int q = 0; q < 2; q++)
            if (kfl[j * 8 + 2 * tg + q] == 2) mask |= 1u << (j * 2 + q);

#pragma unroll
    for (int i = 0; i < 2; i++) {
#pragma unroll
        for (int sel = 0; sel < 2; sel++) {
            float mx = -1e30f;
#pragma unroll
            for (int j = 0; j < 8; j++)
#pragma unroll
                for (int q = 0; q < 2; q++) {
                    float v = c[i][j][sel * 2 + q] * scale;
                    if (mask & (1u << (j * 2 + q))) v = -10000.0f;
                    c[i][j][sel * 2 + q] = v;
                    mx = fmaxf(mx, v);
                }
            mx = fmaxf(mx, __shfl_xor_sync(0xffffffffu, mx, 1));
            mx = fmaxf(mx, __shfl_xor_sync(0xffffffffu, mx, 2));
            float s = 0.0f;
#pragma unroll
            for (int j = 0; j < 8; j++)
#pragma unroll
                for (int q = 0; q < 2; q++) {
                    float e = __expf(c[i][j][sel * 2 + q] - mx);
                    c[i][j][sel * 2 + q] = e;
                    s += e;
                }
            s += __shfl_xor_sync(0xffffffffu, s, 1);
            s += __shfl_xor_sync(0xffffffffu, s, 2);
            float rinv = 1.0f / s;
            int row = rbase + i * 16 + g + sel * 8;
#pragma unroll
            for (int j = 0; j < 8; j++)
#pragma unroll
                for (int q = 0; q < 2; q++)
                    ssh[row * SS3 + j * 8 + 2 * tg + q] = c[i][j][sel * 2 + q] * rinv;
        }
    }
    __syncwarp();

    float o[2][4][4];
#pragma unroll
    for (int i = 0; i < 2; i++)
#pragma unroll
        for (int j = 0; j < 4; j++)
#pragma unroll
            for (int q = 0; q < 4; q++) o[i][j][q] = 0.0f;

#pragma unroll
    for (int kt = 0; kt < 8; kt++) {
        uint32_t a[2][4], b[4][2];
#pragma unroll
        for (int i = 0; i < 2; i++) {
            int row = rbase + i * 16 + g;
            a[i][0] = __float_as_uint(ssh[row * SS3 + kt * 8 + tg]);
            a[i][1] = __float_as_uint(ssh[(row + 8) * SS3 + kt * 8 + tg]);
            a[i][2] = __float_as_uint(ssh[row * SS3 + kt * 8 + tg + 4]);
            a[i][3] = __float_as_uint(ssh[(row + 8) * SS3 + kt * 8 + tg + 4]);
        }
#pragma unroll
        for (int j = 0; j < 4; j++) {
            int n = j * 8 + g;
            b[j][0] = __float_as_uint(qsm[(kt * 8 + tg) * QS3 + bv + n]);
            b[j][1] = __float_as_uint(qsm[(kt * 8 + tg + 4) * QS3 + bv + n]);
        }
#pragma unroll
        for (int i = 0; i < 2; i++)
#pragma unroll
            for (int j = 0; j < 4; j++)
                mma_tf32(o[i][j], a[i], b[j]);
    }

#pragma unroll
    for (int i = 0; i < 2; i++)
#pragma unroll
        for (int j = 0; j < 4; j++) {
            size_t row = (size_t)(m * 64 + rbase + i * 16 + g);
            int col = h * 32 + j * 8 + 2 * tg;
            *reinterpret_cast<__nv_bfloat162*>(&go[row * C_DIM + col]) =
                __floats2bfloat162_rn(o[i][j][0], o[i][j][1]);
            *reinterpret_cast<__nv_bfloat162*>(&go[(row + 8) * C_DIM + col]) =
                __floats2bfloat162_rn(o[i][j][2], o[i][j][3]);
        }
}

// ---------------------------------------------------------------------------
// ybuild (unchanged)
// ---------------------------------------------------------------------------
__global__ void __launch_bounds__(256) ybuild_kernel(
    const float* __restrict__ g1,
    const float* __restrict__ ln2w, const float* __restrict__ ln2b)
{
    int r    = (int)((blockIdx.x * 256u + threadIdx.x) >> 5);
    int lane = threadIdx.x & 31;
    if (r >= A_CNT) return;
    float4 a = reinterpret_cast<const float4*>(g_xa + (size_t)r * C_DIM)[lane];
    float4 t = reinterpret_cast<const float4*>(g_att + (size_t)r * C_DIM)[lane];
    float4 gv = reinterpret_cast<const float4*>(g1)[lane];
    float4 y;
    y.x = a.x + gv.x * t.x; y.y = a.y + gv.y * t.y;
    y.z = a.z + gv.z * t.z; y.w = a.w + gv.w * t.w;
    reinterpret_cast<float4*>(g_y + (size_t)r * C_DIM)[lane] = y;
    float s1 = y.x + y.y + y.z + y.w;
    float s2 = y.x*y.x + y.y*y.y + y.z*y.z + y.w*y.w;
    warp_sum2(s1, s2);
    float m = s1 * (1.0f / C_DIM);
    float var = s2 * (1.0f / C_DIM) - m * m;
    float inv = rsqrtf(var + EPS_LN);
    float4 wv = reinterpret_cast<const float4*>(ln2w)[lane];
    float4 bv = reinterpret_cast<const float4*>(ln2b)[lane];
    __nv_bfloat162 b0 = __floats2bfloat162_rn(
        (y.x - m) * inv * wv.x + bv.x, (y.y - m) * inv * wv.y + bv.y);
    __nv_bfloat162 b1 = __floats2bfloat162_rn(
        (y.z - m) * inv * wv.z + bv.z, (y.w - m) * inv * wv.w + bv.w);
    uint2 u;
    u.x = *reinterpret_cast<uint32_t*>(&b0);
    u.y = *reinterpret_cast<uint32_t*>(&b1);
    *reinterpret_cast<uint2*>(g_yn_bf + (size_t)r * C_DIM + lane * 4) = u;
}

// ---------------------------------------------------------------------------
extern "C" void kernel_launch(void* const* d_in, const int* in_sizes, int n_in,
                              void* d_out, int out_size)
{
    int base = 7;
    if (n_in == 19) base = 5;

    const float* x      = (const float*)d_in[0];
    const int*   iw     = (const int*)d_in[1];
    const int*   ipart  = (const int*)d_in[2];
    const int*   asy    = (const int*)d_in[3];
    const int*   blk    = (const int*)d_in[4];
    const float* ln1w   = (const float*)d_in[base + 0];
    const float* ln1b   = (const float*)d_in[base + 1];
    const float* qkvw   = (const float*)d_in[base + 2];
    const float* qkvb   = (const float*)d_in[base + 3];
    const float* projw  = (const float*)d_in[base + 4];
    const float* projb  = (const float*)d_in[base + 5];
    const float* g1     = (const float*)d_in[base + 6];
    const float* ln2w   = (const float*)d_in[base + 7];
    const float* ln2b   = (const float*)d_in[base + 8];
    const float* w1     = (const float*)d_in[base + 9];
    const float* b1     = (const float*)d_in[base + 10];
    const float* w2     = (const float*)d_in[base + 11];
    const float* b2     = (const float*)d_in[base + 12];
    const float* g2     = (const float*)d_in[base + 13];
    float* out = (float*)d_out;

    __nv_bfloat16 *p_xp, *p_qkv, *p_o, *p_yn, *p_h;
    __nv_bfloat16 *p_wqkvT, *p_wprojT, *p_w1T, *p_w2T;
    cudaGetSymbolAddress((void**)&p_xp, g_xp_bf);
    cudaGetSymbolAddress((void**)&p_qkv, g_qkv_bf);
    cudaGetSymbolAddress((void**)&p_o, g_o_bf);
    cudaGetSymbolAddress((void**)&p_yn, g_yn_bf);
    cudaGetSymbolAddress((void**)&p_h, g_h_bf);
    cudaGetSymbolAddress((void**)&p_wqkvT, g_wqkvT);
    cudaGetSymbolAddress((void**)&p_wprojT, g_wprojT);
    cudaGetSymbolAddress((void**)&p_w1T, g_w1T);
    cudaGetSymbolAddress((void**)&p_w2T, g_w2T);

    cudaFuncSetAttribute(gemm5b_kernel<384, 0>,
                         cudaFuncAttributeMaxDynamicSharedMemorySize, GEMM5B_SMEM_BYTES);
    cudaFuncSetAttribute(gemm5b_kernel<512, 2>,
                         cudaFuncAttributeMaxDynamicSharedMemorySize, GEMM5B_SMEM_BYTES);
    cudaFuncSetAttribute(gemm4b_kernel<128, 1>,
                         cudaFuncAttributeMaxDynamicSharedMemorySize, GEMM4B_SMEM_BYTES);
    cudaFuncSetAttribute(gemm4b_kernel<512, 3>,
                         cudaFuncAttributeMaxDynamicSharedMemorySize, GEMM4B_SMEM_BYTES);
    cudaFuncSetAttribute(attn3_kernel,
                         cudaFuncAttributeMaxDynamicSharedMemorySize, ATTN3_SMEM_BYTES);

    // 0-2. init + maps + meta + weight transposes
    zero_misc_kernel<<<(MW_CNT / 16 + N_WIN / 4 + 255) / 256, 256>>>();
    set_maps_kernel<<<MW_CNT / 256, 256>>>(asy, blk, iw, ipart);
    meta_kernel<<<MW_CNT / 256, 256>>>(ipart, iw);
    wtrans_kernel<<<(128 * 384 + 255) / 256, 256>>>(qkvw, p_wqkvT, 128, 384);
    wtrans_kernel<<<(128 * 128 + 255) / 256, 256>>>(projw, p_wprojT, 128, 128);
    wtrans_kernel<<<(128 * 512 + 255) / 256, 256>>>(w1, p_w1T, 128, 512);
    wtrans_kernel<<<(512 * 128 + 255) / 256, 256>>>(w2, p_w2T, 512, 128);
    // 3. fused LN + double-LN + scatter
    ln_kernel<<<N_TOK / 16, 256>>>(x, ln1w, ln1b, out);
    // 4. QKV GEMM (bf16 MMA, A-resident)
    gemm5b_kernel<384, 0><<<MW_CNT / 128, 256, GEMM5B_SMEM_BYTES>>>(
        p_xp, p_wqkvT, qkvb, p_qkv);
    // 5. attention
    attn3_kernel<<<M_PART, 256, ATTN3_SMEM_BYTES>>>(p_qkv, p_o);
    // 6. proj GEMM (bf16 MMA) + scatter
    gemm4b_kernel<128, 1><<<MW_CNT / 128, 256, GEMM4B_SMEM_BYTES>>>(
        p_o, p_wprojT, projb, out, nullptr);
    // 7. y build + LN2
    ybuild_kernel<<<A_CNT / 8, 256>>>(g1, ln2w, ln2b);
    // 8. MLP GEMM1 (bf16 MMA, A-resident) + gelu
    gemm5b_kernel<512, 2><<<A_CNT / 128, 256, GEMM5B_SMEM_BYTES>>>(
        p_yn, p_w1T, b1, p_h);
    // 9. MLP GEMM2 (bf16 MMA) + residual + scatter
    gemm4b_kernel<512, 3><<<A_CNT / 128, 256, GEMM4B_SMEM_BYTES>>>(
        p_h, p_w2T, b2, out, g2);
}

// round 10
// speedup vs baseline: 1.5137x; 1.2429x over previous
#include <cuda_runtime.h>
#include <cuda_bf16.h>
#include <math.h>
#include <stdint.h>

// Problem constants
#define N_TOK   524288
#define N_WIN   8192
#define P_TOK   64
#define C_DIM   128
#define M_PART  4096
#define MW_CNT  262144
#define A_CNT   131072
#define BL_CNT  65536
#define EPS_LN  1e-6f

// ---------------------------------------------------------------------------
// Scratch (device globals — allocation-free rule)
// ---------------------------------------------------------------------------
__device__ float g_xa[(size_t)A_CNT * C_DIM];
__device__ float g_y[(size_t)A_CNT * C_DIM];
__device__ __nv_bfloat16 g_xp_bf[(size_t)MW_CNT * C_DIM];
__device__ __nv_bfloat16 g_qkv_bf[(size_t)MW_CNT * 384];
__device__ __nv_bfloat16 g_o_bf[(size_t)MW_CNT * C_DIM];
__device__ __nv_bfloat16 g_h_bf[(size_t)A_CNT * 512];
__device__ __nv_bfloat16 g_wqkvT[384 * 128];
__device__ __nv_bfloat16 g_wprojT[128 * 128];
__device__ __nv_bfloat16 g_w1T[512 * 128];
__device__ __nv_bfloat16 g_w2T[128 * 512];
__device__ unsigned char g_flag[MW_CNT];
__device__ int g_rank[MW_CNT];
__device__ int g_ipos[MW_CNT];
__device__ int g_winv[N_WIN];
__device__ int g_asyrow[A_CNT];
__device__ unsigned char g_mflag[MW_CNT];
__device__ int g_mrow[MW_CNT];
__device__ int g_mrank[MW_CNT];

// ---------------------------------------------------------------------------
// helpers
// ---------------------------------------------------------------------------
__device__ __forceinline__ void mma_bf16(float c[4], const uint32_t a[4], const uint32_t b[2]) {
    asm volatile(
        "mma.sync.aligned.m16n8k16.row.col.f32.bf16.bf16.f32 "
        "{%0,%1,%2,%3}, {%4,%5,%6,%7}, {%8,%9}, {%0,%1,%2,%3};"
        : "+f"(c[0]), "+f"(c[1]), "+f"(c[2]), "+f"(c[3])
        : "r"(a[0]), "r"(a[1]), "r"(a[2]), "r"(a[3]), "r"(b[0]), "r"(b[1]));
}
__device__ __forceinline__ uint32_t smem_u32(const void* p) {
    uint32_t a;
    asm("{ .reg .u64 t; cvta.to.shared.u64 t, %1; cvt.u32.u64 %0, t; }" : "=r"(a) : "l"(p));
    return a;
}
__device__ __forceinline__ void cp_async16(uint32_t dst, const void* src) {
    asm volatile("cp.async.cg.shared.global [%0], [%1], 16;" :: "r"(dst), "l"(src) : "memory");
}
__device__ __forceinline__ void warp_sum2(float& s1, float& s2) {
#pragma unroll
    for (int o = 16; o; o >>= 1) {
        s1 += __shfl_xor_sync(0xffffffffu, s1, o);
        s2 += __shfl_xor_sync(0xffffffffu, s2, o);
    }
}
__device__ __forceinline__ void warp_sum4(float& a1, float& a2, float& b1, float& b2) {
#pragma unroll
    for (int o = 16; o; o >>= 1) {
        a1 += __shfl_xor_sync(0xffffffffu, a1, o);
        a2 += __shfl_xor_sync(0xffffffffu, a2, o);
        b1 += __shfl_xor_sync(0xffffffffu, b1, o);
        b2 += __shfl_xor_sync(0xffffffffu, b2, o);
    }
}

// ---------------------------------------------------------------------------
// K0: init
// ---------------------------------------------------------------------------
__global__ void __launch_bounds__(256) zero_misc_kernel()
{
    int t = blockIdx.x * 256 + threadIdx.x;
    if (t < MW_CNT / 16)
        reinterpret_cast<uint4*>(g_flag)[t] = make_uint4(0u, 0u, 0u, 0u);
    int u = t - MW_CNT / 16;
    if (u >= 0 && u < N_WIN / 4)
        reinterpret_cast<int4*>(g_winv)[u] = make_int4(-1, -1, -1, -1);
}

// ---------------------------------------------------------------------------
// K1: index maps
// ---------------------------------------------------------------------------
__global__ void __launch_bounds__(256) set_maps_kernel(
    const int* __restrict__ asy, const int* __restrict__ blk,
    const int* __restrict__ iw, const int* __restrict__ ipart)
{
    int t = blockIdx.x * 256 + threadIdx.x;
    if (t < MW_CNT) g_ipos[ipart[t]] = t;
    if (t < A_CNT) {
        int g = asy[t];
        g_flag[g] = 1;
        g_rank[g] = t;
        g_asyrow[t] = iw[g >> 6] * 64 + (g & 63);
    } else if (t < A_CNT + BL_CNT) {
        g_flag[blk[t - A_CNT]] = 2;
    }
    if (t < M_PART) g_winv[iw[t]] = t;
}

// ---------------------------------------------------------------------------
// K2: partition-order meta
// ---------------------------------------------------------------------------
__global__ void __launch_bounds__(256) meta_kernel(
    const int* __restrict__ ipart, const int* __restrict__ iw)
{
    int i = blockIdx.x * 256 + threadIdx.x;
    if (i >= MW_CNT) return;
    int g = ipart[i];
    int f = g_flag[g];
    g_mflag[i] = (unsigned char)f;
    g_mrow[i]  = iw[g >> 6] * 64 + (g & 63);
    g_mrank[i] = (f == 1) ? g_rank[g] : 0;
}

// ---------------------------------------------------------------------------
// K2b: weight transpose+quantize  W[K,N] fp32 -> WT[N,K] bf16
// ---------------------------------------------------------------------------
__global__ void __launch_bounds__(256) wtrans_kernel(
    const float* __restrict__ W, __nv_bfloat16* __restrict__ WT, int K, int N)
{
    int idx = blockIdx.x * 256 + threadIdx.x;
    if (idx >= K * N) return;
    int k = idx / N, n = idx - k * N;
    WT[n * K + k] = __float2bfloat16(W[idx]);
}

// ---------------------------------------------------------------------------
// K3: fused LN + scatter (2 rows/warp)
// ---------------------------------------------------------------------------
__global__ void __launch_bounds__(256) ln_kernel(
    const float* __restrict__ x, const float* __restrict__ w,
    const float* __restrict__ b, float* __restrict__ out)
{
    int wglob = blockIdx.x * 8 + (threadIdx.x >> 5);
    int lane  = threadIdx.x & 31;
    int r0 = wglob * 2;
    int r1 = r0 + 1;

    float4 v0 = reinterpret_cast<const float4*>(x + (size_t)r0 * C_DIM)[lane];
    float4 v1 = reinterpret_cast<const float4*>(x + (size_t)r1 * C_DIM)[lane];
    float4 wv = reinterpret_cast<const float4*>(w)[lane];
    float4 bv = reinterpret_cast<const float4*>(b)[lane];

    float a1 = v0.x + v0.y + v0.z + v0.w;
    float a2 = v0.x*v0.x + v0.y*v0.y + v0.z*v0.z + v0.w*v0.w;
    float c1 = v1.x + v1.y + v1.z + v1.w;
    float c2 = v1.x*v1.x + v1.y*v1.y + v1.z*v1.z + v1.w*v1.w;
    warp_sum4(a1, a2, c1, c2);

#pragma unroll
    for (int rr = 0; rr < 2; rr++) {
        int row = rr ? r1 : r0;
        float4 v = rr ? v1 : v0;
        float s1 = rr ? c1 : a1;
        float s2 = rr ? c2 : a2;
        float m = s1 * (1.0f / C_DIM);
        float var = s2 * (1.0f / C_DIM) - m * m;
        float inv = rsqrtf(var + EPS_LN);
        float4 r;
        r.x = (v.x - m) * inv * wv.x + bv.x; r.y = (v.y - m) * inv * wv.y + bv.y;
        r.z = (v.z - m) * inv * wv.z + bv.z; r.w = (v.w - m) * inv * wv.w + bv.w;

        int n = row >> 6, p = row & 63;
        int widx = g_winv[n];
        if (widx < 0) {
            reinterpret_cast<float4*>(out + (size_t)row * C_DIM)[lane] = r;
        } else {
            int g = widx * 64 + p;
            int f = g_flag[g];
            int ipos = g_ipos[g];
            float4 val = r;
            if (f == 2) {
                reinterpret_cast<float4*>(out + (size_t)row * C_DIM)[lane] = r;
            } else if (f == 1) {
                float t1 = r.x + r.y + r.z + r.w;
                float t2 = r.x*r.x + r.y*r.y + r.z*r.z + r.w*r.w;
                warp_sum2(t1, t2);
                float m2 = t1 * (1.0f / C_DIM);
                float var2 = t2 * (1.0f / C_DIM) - m2 * m2;
                float inv2 = rsqrtf(var2 + EPS_LN);
                val.x = (r.x - m2) * inv2 * wv.x + bv.x;
                val.y = (r.y - m2) * inv2 * wv.y + bv.y;
                val.z = (r.z - m2) * inv2 * wv.z + bv.z;
                val.w = (r.w - m2) * inv2 * wv.w + bv.w;
                reinterpret_cast<float4*>(g_xa + (size_t)g_rank[g] * C_DIM)[lane] = val;
            }
            __nv_bfloat162 b0 = __floats2bfloat162_rn(val.x, val.y);
            __nv_bfloat162 b1 = __floats2bfloat162_rn(val.z, val.w);
            uint2 u;
            u.x = *reinterpret_cast<uint32_t*>(&b0);
            u.y = *reinterpret_cast<uint32_t*>(&b1);
            *reinterpret_cast<uint2*>(g_xp_bf + (size_t)ipos * C_DIM + lane * 4) = u;
        }
    }
}

// ---------------------------------------------------------------------------
// GEMM5B: bf16 m16n8k16, A-resident.  AMODE 0: bf16 cp.async A panel.
// AMODE 1: load g_y fp32, LN2 per row, convert -> bf16 panel (MLP1).
//   EPI 0: +bias   EPI 2: +bias+gelu
// ---------------------------------------------------------------------------
#define SA5W 68
#define SB5W 20
#define B5WORDS (128 * SB5W)
#define GEMM5B_SMEM_BYTES ((128 * SA5W + 2 * B5WORDS) * 4)

template<int NTOT, int EPI, int AMODE>
__global__ void __launch_bounds__(256) gemm5b_kernel(
    const __nv_bfloat16* __restrict__ Ab, const __nv_bfloat16* __restrict__ WT,
    const float* __restrict__ bias, __nv_bfloat16* __restrict__ outb,
    const float* __restrict__ ln2w, const float* __restrict__ ln2b)
{
    extern __shared__ uint32_t smu[];
    uint32_t* As = smu;
    uint32_t* Bs = smu + 128 * SA5W;

    int tid  = threadIdx.x;
    int lane = tid & 31;
    int wid  = tid >> 5;
    int wr   = wid >> 1;
    int wc   = wid & 1;
    int g    = lane >> 2;
    int tg   = lane & 3;
    size_t m0 = (size_t)blockIdx.x * 128;

    uint32_t as_u = smem_u32(As);
    uint32_t bs_u = smem_u32(Bs);

    auto loadB = [&](int nc, int kc, int s) {
#pragma unroll
        for (int t = 0; t < 2; t++) {
            int idx = tid + t * 256;
            int r = idx >> 2, cc = idx & 3;
            cp_async16(bs_u + (uint32_t)(s * (B5WORDS * 4) + r * (SB5W * 4) + cc * 16),
                       WT + (size_t)(nc * 128 + r) * C_DIM + kc * 32 + cc * 8);
        }
        asm volatile("cp.async.commit_group;" ::: "memory");
    };

    if constexpr (AMODE == 0) {
#pragma unroll
        for (int t = 0; t < 8; t++) {
            int idx = tid + t * 256;
            int r = idx >> 4, cc = idx & 15;
            cp_async16(as_u + (uint32_t)(r * (SA5W * 4) + cc * 16),
                       Ab + (m0 + r) * C_DIM + cc * 8);
        }
        loadB(0, 0, 0);   // A + B(0) in one group
    } else {
        loadB(0, 0, 0);
        // LN2 over g_y rows -> bf16 A panel.  warp handles 16 rows.
        float4 wv = reinterpret_cast<const float4*>(ln2w)[lane];
        float4 bv = reinterpret_cast<const float4*>(ln2b)[lane];
        for (int it = 0; it < 16; it++) {
            int r = wid * 16 + it;
            float4 v = reinterpret_cast<const float4*>(
                g_y + (m0 + r) * C_DIM)[lane];
            float s1 = v.x + v.y + v.z + v.w;
            float s2 = v.x*v.x + v.y*v.y + v.z*v.z + v.w*v.w;
            warp_sum2(s1, s2);
            float m = s1 * (1.0f / C_DIM);
            float var = s2 * (1.0f / C_DIM) - m * m;
            float inv = rsqrtf(var + EPS_LN);
            __nv_bfloat162 p0 = __floats2bfloat162_rn(
                (v.x - m) * inv * wv.x + bv.x, (v.y - m) * inv * wv.y + bv.y);
            __nv_bfloat162 p1 = __floats2bfloat162_rn(
                (v.z - m) * inv * wv.z + bv.z, (v.w - m) * inv * wv.w + bv.w);
            As[r * SA5W + lane * 2]     = *reinterpret_cast<uint32_t*>(&p0);
            As[r * SA5W + lane * 2 + 1] = *reinterpret_cast<uint32_t*>(&p1);
        }
    }

    constexpr int NCH = NTOT / 128;
#pragma unroll 1
    for (int nc = 0; nc < NCH; nc++) {
        if (nc > 0) loadB(nc, 0, 0);
        float c[2][8][4];
#pragma unroll
        for (int i = 0; i < 2; i++)
#pragma unroll
            for (int j = 0; j < 8; j++)
#pragma unroll
                for (int q = 0; q < 4; q++) c[i][j][q] = 0.0f;

#pragma unroll
        for (int kc = 0; kc < 4; kc++) {
            int s = kc & 1;
            if (kc < 3) {
                loadB(nc, kc + 1, s ^ 1);
                asm volatile("cp.async.wait_group 1;" ::: "memory");
            } else {
                asm volatile("cp.async.wait_group 0;" ::: "memory");
            }
            __syncthreads();
            const uint32_t* Bp = Bs + s * B5WORDS;
#pragma unroll
            for (int kk = 0; kk < 2; kk++) {
                int kw = kc * 16 + kk * 8 + tg;
                uint32_t a[2][4], b[8][2];
#pragma unroll
                for (int i = 0; i < 2; i++) {
                    int row = wr * 32 + i * 16 + g;
                    a[i][0] = As[row * SA5W + kw];
                    a[i][1] = As[(row + 8) * SA5W + kw];
                    a[i][2] = As[row * SA5W + kw + 4];
                    a[i][3] = As[(row + 8) * SA5W + kw + 4];
                }
#pragma unroll
                for (int j = 0; j < 8; j++) {
                    int n = wc * 64 + j * 8 + g;
                    b[j][0] = Bp[n * SB5W + kk * 8 + tg];
                    b[j][1] = Bp[n * SB5W + kk * 8 + tg + 4];
                }
#pragma unroll
                for (int i = 0; i < 2; i++)
#pragma unroll
                    for (int j = 0; j < 8; j++)
                        mma_bf16(c[i][j], a[i], b[j]);
            }
            __syncthreads();
        }

#pragma unroll
        for (int i = 0; i < 2; i++) {
#pragma unroll
            for (int half = 0; half < 2; half++) {
                size_t grow = m0 + wr * 32 + i * 16 + g + half * 8;
#pragma unroll
                for (int j = 0; j < 8; j++) {
                    int colg = nc * 128 + wc * 64 + j * 8 + tg * 2;
                    float v0 = c[i][j][half * 2]     + __ldg(&bias[colg]);
                    float v1 = c[i][j][half * 2 + 1] + __ldg(&bias[colg + 1]);
                    if constexpr (EPI == 2) {
                        v0 = 0.5f * v0 * (1.0f + erff(v0 * 0.7071067811865476f));
                        v1 = 0.5f * v1 * (1.0f + erff(v1 * 0.7071067811865476f));
                    }
                    *reinterpret_cast<__nv_bfloat162*>(outb + grow * NTOT + colg) =
                        __floats2bfloat162_rn(v0, v1);
                }
            }
        }
    }
}

// ---------------------------------------------------------------------------
// GEMM4B: bf16 m16n8k16, streaming K, NTOT=128.
//   EPI 1: proj — f==1: g_y[rank] = xa + evec*(acc+bias); f==0: out[row]
//   EPI 3: out[g_asyrow] = g_y + evec*(acc+bias)
// ---------------------------------------------------------------------------
#define S4W 20
#define A4WORDS (128 * S4W)
#define B4WORDS (128 * S4W)
#define GEMM4B_SMEM_BYTES ((2 * A4WORDS + 2 * B4WORDS) * 4)

template<int KTOT, int EPI>
__global__ void __launch_bounds__(256) gemm4b_kernel(
    const __nv_bfloat16* __restrict__ Ab, const __nv_bfloat16* __restrict__ WT,
    const float* __restrict__ bias, float* __restrict__ outv,
    const float* __restrict__ evec)
{
    extern __shared__ uint32_t smu[];
    uint32_t* As = smu;
    uint32_t* Bs = smu + 2 * A4WORDS;

    int tid  = threadIdx.x;
    int lane = tid & 31;
    int wid  = tid >> 5;
    int wr   = wid >> 1;
    int wc   = wid & 1;
    int g    = lane >> 2;
    int tg   = lane & 3;
    size_t m0 = (size_t)blockIdx.x * 128;
    constexpr int NC = KTOT / 32;

    uint32_t as_u = smem_u32(As);
    uint32_t bs_u = smem_u32(Bs);

    auto loadAB = [&](int kc, int s) {
#pragma unroll
        for (int t = 0; t < 2; t++) {
            int idx = tid + t * 256;
            int r = idx >> 2, cc = idx & 3;
            cp_async16(as_u + (uint32_t)(s * (A4WORDS * 4) + r * (S4W * 4) + cc * 16),
                       Ab + (m0 + r) * KTOT + kc * 32 + cc * 8);
        }
#pragma unroll
        for (int t = 0; t < 2; t++) {
            int idx = tid + t * 256;
            int r = idx >> 2, cc = idx & 3;
            cp_async16(bs_u + (uint32_t)(s * (B4WORDS * 4) + r * (S4W * 4) + cc * 16),
                       WT + (size_t)r * KTOT + kc * 32 + cc * 8);
        }
        asm volatile("cp.async.commit_group;" ::: "memory");
    };

    float c[2][8][4];
#pragma unroll
    for (int i = 0; i < 2; i++)
#pragma unroll
        for (int j = 0; j < 8; j++)
#pragma unroll
            for (int q = 0; q < 4; q++) c[i][j][q] = 0.0f;

    loadAB(0, 0);
#pragma unroll 1
    for (int kc = 0; kc < NC; kc++) {
        int s = kc & 1;
        if (kc + 1 < NC) {
            loadAB(kc + 1, s ^ 1);
            asm volatile("cp.async.wait_group 1;" ::: "memory");
        } else {
            asm volatile("cp.async.wait_group 0;" ::: "memory");
        }
        __syncthreads();
        const uint32_t* Ap = As + s * A4WORDS;
        const uint32_t* Bp = Bs + s * B4WORDS;
#pragma unroll
        for (int kk = 0; kk < 2; kk++) {
            uint32_t a[2][4], b[8][2];
#pragma unroll
            for (int i = 0; i < 2; i++) {
                int row = wr * 32 + i * 16 + g;
                a[i][0] = Ap[row * S4W + kk * 8 + tg];
                a[i][1] = Ap[(row + 8) * S4W + kk * 8 + tg];
                a[i][2] = Ap[row * S4W + kk * 8 + tg + 4];
                a[i][3] = Ap[(row + 8) * S4W + kk * 8 + tg + 4];
            }
#pragma unroll
            for (int j = 0; j < 8; j++) {
                int n = wc * 64 + j * 8 + g;
                b[j][0] = Bp[n * S4W + kk * 8 + tg];
                b[j][1] = Bp[n * S4W + kk * 8 + tg + 4];
            }
#pragma unroll
            for (int i = 0; i < 2; i++)
#pragma unroll
                for (int j = 0; j < 8; j++)
                    mma_bf16(c[i][j], a[i], b[j]);
        }
        __syncthreads();
    }

#pragma unroll
    for (int i = 0; i < 2; i++) {
#pragma unroll
        for (int half = 0; half < 2; half++) {
            size_t grow = m0 + wr * 32 + i * 16 + g + half * 8;
            if constexpr (EPI == 1) {
                int f = g_mflag[grow];
                if (f == 2) continue;
                if (f == 1) {
                    size_t rank = (size_t)g_mrank[grow];
#pragma unroll
                    for (int j = 0; j < 8; j++) {
                        int colg = wc * 64 + j * 8 + tg * 2;
                        float v0 = c[i][j][half * 2]     + __ldg(&bias[colg]);
                        float v1 = c[i][j][half * 2 + 1] + __ldg(&bias[colg + 1]);
                        v0 = g_xa[rank * C_DIM + colg]     + __ldg(&evec[colg]) * v0;
                        v1 = g_xa[rank * C_DIM + colg + 1] + __ldg(&evec[colg + 1]) * v1;
                        *reinterpret_cast<float2*>(g_y + rank * C_DIM + colg) =
                            make_float2(v0, v1);
                    }
                } else {
                    float* dstf = outv + (size_t)g_mrow[grow] * C_DIM;
#pragma unroll
                    for (int j = 0; j < 8; j++) {
                        int colg = wc * 64 + j * 8 + tg * 2;
                        float v0 = c[i][j][half * 2]     + __ldg(&bias[colg]);
                        float v1 = c[i][j][half * 2 + 1] + __ldg(&bias[colg + 1]);
                        *reinterpret_cast<float2*>(dstf + colg) = make_float2(v0, v1);
                    }
                }
            } else {
                float* dstf = outv + (size_t)g_asyrow[grow] * C_DIM;
#pragma unroll
                for (int j = 0; j < 8; j++) {
                    int colg = wc * 64 + j * 8 + tg * 2;
                    float v0 = c[i][j][half * 2]     + __ldg(&bias[colg]);
                    float v1 = c[i][j][half * 2 + 1] + __ldg(&bias[colg + 1]);
                    v0 = g_y[grow * C_DIM + colg]     + __ldg(&evec[colg]) * v0;
                    v1 = g_y[grow * C_DIM + colg + 1] + __ldg(&evec[colg + 1]) * v1;
                    *reinterpret_cast<float2*>(dstf + colg) = make_float2(v0, v1);
                }
            }
        }
    }
}

// ---------------------------------------------------------------------------
// attn4: full-bf16 attention per partition. g_qkv_bf (64x384) -> g_o_bf.
//   qsm: 64 rows x 196 words (392 bf16, row = 384 qkv + pad)
//   P:   4 heads x 64 rows x 36 words (72 bf16)
//   VT:  4 heads x 32 rows x 36 words ([d][key] bf16)
// ---------------------------------------------------------------------------
#define QW4 196
#define PW4 36
#define QSM_W (64 * QW4)
#define P_W   (4 * 64 * PW4)
#define VT_W  (4 * 32 * PW4)
#define ATTN4_SMEM_BYTES ((QSM_W + P_W + VT_W + 64) * 4)

__global__ void __launch_bounds__(256) attn4_kernel(
    const __nv_bfloat16* __restrict__ gqkv, __nv_bfloat16* __restrict__ go)
{
    extern __shared__ uint32_t smu[];
    uint32_t* qw = smu;                 // QSM_W
    uint32_t* pw = smu + QSM_W;         // P_W
    uint32_t* vtw = pw + P_W;           // VT_W
    int* kfl = (int*)(vtw + VT_W);

    int m   = blockIdx.x;
    int tid = threadIdx.x;
    uint32_t q_u = smem_u32(qw);

    if (tid < 64) kfl[tid] = g_mflag[m * 64 + tid];

    // stage qkv bf16 directly: 64 rows x 768 B = 3072 16B txns
    for (int i = tid; i < 3072; i += 256) {
        int r = i / 48, t = i - r * 48;
        cp_async16(q_u + (uint32_t)(r * (QW4 * 4) + t * 16),
                   gqkv + (size_t)m * 24576 + r * 384 + t * 8);
    }
    asm volatile("cp.async.commit_group;" ::: "memory");
    asm volatile("cp.async.wait_group 0;" ::: "memory");
    __syncthreads();

    // build VT[h][d][key] bf16 from qsm V region
    {
        const __nv_bfloat16* qb = reinterpret_cast<const __nv_bfloat16*>(qw);
        __nv_bfloat16* vtb = reinterpret_cast<__nv_bfloat16*>(vtw);
        for (int i = tid; i < 8192; i += 256) {
            int key = i >> 7, d = i & 127;
            int h = d >> 5, dd = d & 31;
            vtb[h * 2304 + dd * 72 + key] = qb[key * 392 + h * 96 + 64 + d - h * 32 * 1];
        }
    }
    __syncthreads();

    int wid = tid >> 5, lane = tid & 31;
    int g = lane >> 2, tg = lane & 3;
    int h = wid >> 1;
    int rbase = (wid & 1) * 32;
    int qh = h * 48;          // Q word base in row
    int kh = h * 48 + 16;     // K word base
    uint32_t* ph = pw + h * 64 * PW4;
    const uint32_t* vth = vtw + h * 32 * PW4;
    const float scale = 0.17677669529663687f;

    // ---- S = Q K^T (bf16, k=32 -> 2 k16 steps) ----
    float c[2][8][4];
#pragma unroll
    for (int i = 0; i < 2; i++)
#pragma unroll
        for (int j = 0; j < 8; j++)
#pragma unroll
            for (int q = 0; q < 4; q++) c[i][j][q] = 0.0f;

#pragma unroll
    for (int kq = 0; kq < 2; kq++) {
        uint32_t a[2][4], b[8][2];
#pragma unroll
        for (int i = 0; i < 2; i++) {
            int row = rbase + i * 16 + g;
            a[i][0] = qw[row * QW4 + qh + kq * 8 + tg];
            a[i][1] = qw[(row + 8) * QW4 + qh + kq * 8 + tg];
            a[i][2] = qw[row * QW4 + qh + kq * 8 + tg + 4];
            a[i][3] = qw[(row + 8) * QW4 + qh + kq * 8 + tg + 4];
        }
#pragma unroll
        for (int j = 0; j < 8; j++) {
            int n = j * 8 + g;
            b[j][0] = qw[n * QW4 + kh + kq * 8 + tg];
            b[j][1] = qw[n * QW4 + kh + kq * 8 + tg + 4];
        }
#pragma unroll
        for (int i = 0; i < 2; i++)
#pragma unroll
            for (int j = 0; j < 8; j++)
                mma_bf16(c[i][j], a[i], b[j]);
    }

    // ---- mask + register softmax ----
    unsigned mask = 0;
#pragma unroll
    for (int j = 0; j < 8; j++)
#pragma unroll
        for (int q = 0; q < 2; q++)
            if (kfl[j * 8 + 2 * tg + q] == 2) mask |= 1u << (j * 2 + q);

#pragma unroll
    for (int i = 0; i < 2; i++) {
#pragma unroll
        for (int sel = 0; sel < 2; sel++) {
            float mx = -1e30f;
#pragma unroll
            for (int j = 0; j < 8; j++)
#pragma unroll
                for (int q = 0; q < 2; q++) {
                    float v = c[i][j][sel * 2 + q] * scale;
                    if (mask & (1u << (j * 2 + q))) v = -10000.0f;
                    c[i][j][sel * 2 + q] = v;
                    mx = fmaxf(mx, v);
                }
            mx = fmaxf(mx, __shfl_xor_sync(0xffffffffu, mx, 1));
            mx = fmaxf(mx, __shfl_xor_sync(0xffffffffu, mx, 2));
            float s = 0.0f;
#pragma unroll
            for (int j = 0; j < 8; j++)
#pragma unroll
                for (int q = 0; q < 2; q++) {
                    float e = __expf(c[i][j][sel * 2 + q] - mx);
                    c[i][j][sel * 2 + q] = e;
                    s += e;
                }
            s += __shfl_xor_sync(0xffffffffu, s, 1);
            s += __shfl_xor_sync(0xffffffffu, s, 2);
            float rinv = 1.0f / s;
            int row = rbase + i * 16 + g + sel * 8;
#pragma unroll
            for (int j = 0; j < 8; j++) {
                __nv_bfloat162 pk = __floats2bfloat162_rn(
                    c[i][j][sel * 2] * rinv, c[i][j][sel * 2 + 1] * rinv);
                ph[row * PW4 + j * 4 + tg] = *reinterpret_cast<uint32_t*>(&pk);
            }
        }
    }
    __syncwarp();

    // ---- O = P @ V^T (bf16, k=64 -> 4 k16 steps, n=32) ----
    float o[2][4][4];
#pragma unroll
    for (int i = 0; i < 2; i++)
#pragma unroll
        for (int j = 0; j < 4; j++)
#pragma unroll
            for (int q = 0; q < 4; q++) o[i][j][q] = 0.0f;

#pragma unroll
    for (int kp = 0; kp < 4; kp++) {
        uint32_t a[2][4], b[4][2];
#pragma unroll
        for (int i = 0; i < 2; i++) {
            int row = rbase + i * 16 + g;
            a[i][0] = ph[row * PW4 + kp * 8 + tg];
            a[i][1] = ph[(row + 8) * PW4 + kp * 8 + tg];
            a[i][2] = ph[row * PW4 + kp * 8 + tg + 4];
            a[i][3] = ph[(row + 8) * PW4 + kp * 8 + tg + 4];
        }
#pragma unroll
        for (int j = 0; j < 4; j++) {
            int n = j * 8 + g;
            b[j][0] = vth[n * PW4 + kp * 8 + tg];
            b[j][1] = vth[n * PW4 + kp * 8 + tg + 4];
        }
#pragma unroll
        for (int i = 0; i < 2; i++)
#pragma unroll
            for (int j = 0; j < 4; j++)
                mma_bf16(o[i][j], a[i], b[j]);
    }

#pragma unroll
    for (int i = 0; i < 2; i++)
#pragma unroll
        for (int j = 0; j < 4; j++) {
            size_t row = (size_t)(m * 64 + rbase + i * 16 + g);
            int col = h * 32 + j * 8 + 2 * tg;
            *reinterpret_cast<__nv_bfloat162*>(&go[row * C_DIM + col]) =
                __floats2bfloat162_rn(o[i][j][0], o[i][j][1]);
            *reinterpret_cast<__nv_bfloat162*>(&go[(row + 8) * C_DIM + col]) =
                __floats2bfloat162_rn(o[i][j][2], o[i][j][3]);
        }
}

// ---------------------------------------------------------------------------
extern "C" void kernel_launch(void* const* d_in, const int* in_sizes, int n_in,
                              void* d_out, int out_size)
{
    int base = 7;
    if (n_in == 19) base = 5;

    const float* x      = (const float*)d_in[0];
    const int*   iw     = (const int*)d_in[1];
    const int*   ipart  = (const int*)d_in[2];
    const int*   asy    = (const int*)d_in[3];
    const int*   blk    = (const int*)d_in[4];
    const float* ln1w   = (const float*)d_in[base + 0];
    const float* ln1b   = (const float*)d_in[base + 1];
    const float* qkvw   = (const float*)d_in[base + 2];
    const float* qkvb   = (const float*)d_in[base + 3];
    const float* projw  = (const float*)d_in[base + 4];
    const float* projb  = (const float*)d_in[base + 5];
    const float* g1     = (const float*)d_in[base + 6];
    const float* ln2w   = (const float*)d_in[base + 7];
    const float* ln2b   = (const float*)d_in[base + 8];
    const float* w1     = (const float*)d_in[base + 9];
    const float* b1     = (const float*)d_in[base + 10];
    const float* w2     = (const float*)d_in[base + 11];
    const float* b2     = (const float*)d_in[base + 12];
    const float* g2     = (const float*)d_in[base + 13];
    float* out = (float*)d_out;

    __nv_bfloat16 *p_xp, *p_qkv, *p_o, *p_h;
    __nv_bfloat16 *p_wqkvT, *p_wprojT, *p_w1T, *p_w2T;
    cudaGetSymbolAddress((void**)&p_xp, g_xp_bf);
    cudaGetSymbolAddress((void**)&p_qkv, g_qkv_bf);
    cudaGetSymbolAddress((void**)&p_o, g_o_bf);
    cudaGetSymbolAddress((void**)&p_h, g_h_bf);
    cudaGetSymbolAddress((void**)&p_wqkvT, g_wqkvT);
    cudaGetSymbolAddress((void**)&p_wprojT, g_wprojT);
    cudaGetSymbolAddress((void**)&p_w1T, g_w1T);
    cudaGetSymbolAddress((void**)&p_w2T, g_w2T);

    cudaFuncSetAttribute(gemm5b_kernel<384, 0, 0>,
                         cudaFuncAttributeMaxDynamicSharedMemorySize, GEMM5B_SMEM_BYTES);
    cudaFuncSetAttribute(gemm5b_kernel<512, 2, 1>,
                         cudaFuncAttributeMaxDynamicSharedMemorySize, GEMM5B_SMEM_BYTES);
    cudaFuncSetAttribute(gemm4b_kernel<128, 1>,
                         cudaFuncAttributeMaxDynamicSharedMemorySize, GEMM4B_SMEM_BYTES);
    cudaFuncSetAttribute(gemm4b_kernel<512, 3>,
                         cudaFuncAttributeMaxDynamicSharedMemorySize, GEMM4B_SMEM_BYTES);
    cudaFuncSetAttribute(attn4_kernel,
                         cudaFuncAttributeMaxDynamicSharedMemorySize, ATTN4_SMEM_BYTES);

    // 0-2. init + maps + meta + weight transposes
    zero_misc_kernel<<<(MW_CNT / 16 + N_WIN / 4 + 255) / 256, 256>>>();
    set_maps_kernel<<<MW_CNT / 256, 256>>>(asy, blk, iw, ipart);
    meta_kernel<<<MW_CNT / 256, 256>>>(ipart, iw);
    wtrans_kernel<<<(128 * 384 + 255) / 256, 256>>>(qkvw, p_wqkvT, 128, 384);
    wtrans_kernel<<<(128 * 128 + 255) / 256, 256>>>(projw, p_wprojT, 128, 128);
    wtrans_kernel<<<(128 * 512 + 255) / 256, 256>>>(w1, p_w1T, 128, 512);
    wtrans_kernel<<<(512 * 128 + 255) / 256, 256>>>(w2, p_w2T, 512, 128);
    // 3. fused LN + double-LN + scatter
    ln_kernel<<<N_TOK / 16, 256>>>(x, ln1w, ln1b, out);
    // 4. QKV GEMM
    gemm5b_kernel<384, 0, 0><<<MW_CNT / 128, 256, GEMM5B_SMEM_BYTES>>>(
        p_xp, p_wqkvT, qkvb, p_qkv, nullptr, nullptr);
    // 5. attention (bf16 MMA)
    attn4_kernel<<<M_PART, 256, ATTN4_SMEM_BYTES>>>(p_qkv, p_o);
    // 6. proj GEMM + fused y-build (g_y = xa + g1*proj) / scatter
    gemm4b_kernel<128, 1><<<MW_CNT / 128, 256, GEMM4B_SMEM_BYTES>>>(
        p_o, p_wprojT, projb, out, g1);
    // 7. MLP GEMM1 (LN2 fused into A-load) + gelu
    gemm5b_kernel<512, 2, 1><<<A_CNT / 128, 256, GEMM5B_SMEM_BYTES>>>(
        nullptr, p_w1T, b1, p_h, ln2w, ln2b);
    // 8. MLP GEMM2 + residual + scatter
    gemm4b_kernel<512, 3><<<A_CNT / 128, 256, GEMM4B_SMEM_BYTES>>>(
        p_h, p_w2T, b2, out, g2);
}